// round 4
// baseline (speedup 1.0000x reference)
#include <cuda_runtime.h>
#include <math.h>

// ---------------- problem dims ----------------
#define BB    2
#define SS    2048
#define HID   2048
#define PDIM  12288          // 2*KEY + 2*VAL
#define VDIM  4096
#define KEYD  2048           // NK*DK
#define NVH   32
#define ROWS  4096           // B*S

// ---------------- static scratch (no cudaMalloc allowed) ----------------
__device__ float g_qkvz[(size_t)ROWS * PDIM];   // 201 MB
__device__ float g_ba  [ROWS * 64];
__device__ float g_qn  [(size_t)ROWS * KEYD];   // normalized q
__device__ float g_kn  [(size_t)ROWS * KEYD];   // normalized k
__device__ float g_v   [(size_t)ROWS * VDIM];   // v after conv+silu; reused as gated buffer
__device__ float g_beta[ROWS * NVH];
__device__ float g_ge  [ROWS * NVH];
__device__ float g_core[(size_t)ROWS * VDIM];

// ---------------- helpers ----------------
__device__ __forceinline__ unsigned f2tf32(float x) {
    unsigned r;
    asm("cvt.rna.tf32.f32 %0, %1;" : "=r"(r) : "f"(x));
    return r;
}

__device__ __forceinline__ void mma_tf32(float* d, const unsigned* a, const unsigned* b) {
    asm volatile(
        "mma.sync.aligned.m16n8k8.row.col.f32.tf32.tf32.f32 "
        "{%0,%1,%2,%3}, {%4,%5,%6,%7}, {%8,%9}, {%0,%1,%2,%3};"
        : "+f"(d[0]), "+f"(d[1]), "+f"(d[2]), "+f"(d[3])
        : "r"(a[0]), "r"(a[1]), "r"(a[2]), "r"(a[3]), "r"(b[0]), "r"(b[1]));
}

// =====================================================================
// TF32 GEMM: C[M,N] = A[M,K] * B[N,K]^T   (all row-major fp32)
// M,N multiples of 128, K multiple of 32. 256 threads, 128x128x32 tiles.
// =====================================================================
__global__ __launch_bounds__(256) void gemm_tf32(
    const float* __restrict__ A, const float* __restrict__ B,
    float* __restrict__ C, int M, int N, int K)
{
    __shared__ unsigned As[128][36];
    __shared__ unsigned Bs[128][36];

    const int tid  = threadIdx.x;
    const int bm   = blockIdx.y * 128;
    const int bn   = blockIdx.x * 128;
    const int warp = tid >> 5, lane = tid & 31;
    const int wm   = (warp & 1) * 64;   // 2 warps along M (64 rows each)
    const int wn   = (warp >> 1) * 32;  // 4 warps along N (32 cols each)

    const int lr = tid >> 3;            // load row 0..31 (x4 passes)
    const int lc = (tid & 7) * 4;       // load col 0..28

    float acc[4][4][4];
#pragma unroll
    for (int i = 0; i < 4; i++)
#pragma unroll
        for (int j = 0; j < 4; j++)
#pragma unroll
            for (int r = 0; r < 4; r++) acc[i][j][r] = 0.f;

    float4 ra[4], rb[4];
#pragma unroll
    for (int p = 0; p < 4; p++) {
        ra[p] = *(const float4*)(A + (size_t)(bm + lr + p * 32) * K + lc);
        rb[p] = *(const float4*)(B + (size_t)(bn + lr + p * 32) * K + lc);
    }

    for (int kt = 0; kt < K; kt += 32) {
#pragma unroll
        for (int p = 0; p < 4; p++) {
            uint4 ua; ua.x = f2tf32(ra[p].x); ua.y = f2tf32(ra[p].y);
                      ua.z = f2tf32(ra[p].z); ua.w = f2tf32(ra[p].w);
            *(uint4*)&As[lr + p * 32][lc] = ua;
            uint4 ub; ub.x = f2tf32(rb[p].x); ub.y = f2tf32(rb[p].y);
                      ub.z = f2tf32(rb[p].z); ub.w = f2tf32(rb[p].w);
            *(uint4*)&Bs[lr + p * 32][lc] = ub;
        }
        __syncthreads();

        if (kt + 32 < K) {
#pragma unroll
            for (int p = 0; p < 4; p++) {
                ra[p] = *(const float4*)(A + (size_t)(bm + lr + p * 32) * K + kt + 32 + lc);
                rb[p] = *(const float4*)(B + (size_t)(bn + lr + p * 32) * K + kt + 32 + lc);
            }
        }

#pragma unroll
        for (int kk = 0; kk < 4; kk++) {
            const int k0 = kk * 8;
            unsigned af[4][4], bf[4][2];
            const int cc = k0 + (lane & 3);
#pragma unroll
            for (int i = 0; i < 4; i++) {
                const int r = wm + i * 16 + (lane >> 2);
                af[i][0] = As[r][cc];     af[i][1] = As[r + 8][cc];
                af[i][2] = As[r][cc + 4]; af[i][3] = As[r + 8][cc + 4];
            }
#pragma unroll
            for (int j = 0; j < 4; j++) {
                const int n = wn + j * 8 + (lane >> 2);
                bf[j][0] = Bs[n][cc]; bf[j][1] = Bs[n][cc + 4];
            }
#pragma unroll
            for (int i = 0; i < 4; i++)
#pragma unroll
                for (int j = 0; j < 4; j++)
                    mma_tf32(acc[i][j], af[i], bf[j]);
        }
        __syncthreads();
    }

#pragma unroll
    for (int i = 0; i < 4; i++)
#pragma unroll
        for (int j = 0; j < 4; j++) {
            const int r = bm + wm + i * 16 + (lane >> 2);
            const int c = bn + wn + j * 8 + (lane & 3) * 2;
            float2 v0; v0.x = acc[i][j][0]; v0.y = acc[i][j][1];
            float2 v1; v1.x = acc[i][j][2]; v1.y = acc[i][j][3];
            *(float2*)(C + (size_t)r * N + c)       = v0;
            *(float2*)(C + (size_t)(r + 8) * N + c) = v1;
        }
}

// =====================================================================
// ba = x @ W_ba^T  -> g_ba [ROWS, 64]. Warp per output element.
// =====================================================================
__global__ __launch_bounds__(256) void ba_gemm(
    const float* __restrict__ x, const float* __restrict__ W_ba)
{
    const int warp = threadIdx.x >> 5, lane = threadIdx.x & 31;
    const int gid  = blockIdx.x * 8 + warp;          // 0 .. 4096*64-1
    const int row  = gid >> 6;
    const int p    = gid & 63;
    const float* xr = x + (size_t)row * HID;
    const float* wr = W_ba + (size_t)p * HID;
    float acc = 0.f;
#pragma unroll 8
    for (int i = 0; i < HID / 32; i++)
        acc = fmaf(xr[i * 32 + lane], wr[i * 32 + lane], acc);
#pragma unroll
    for (int off = 16; off; off >>= 1)
        acc += __shfl_xor_sync(0xFFFFFFFFu, acc, off);
    if (lane == 0) g_ba[row * 64 + p] = acc;
}

// =====================================================================
// Causal depthwise conv (K=4) + SiLU + split + l2norm(q,k per head)
// grid (64, S, B), block 128: one block = one 128-channel group = one head
// =====================================================================
__global__ __launch_bounds__(128) void conv_norm(const float* __restrict__ conv_w)
{
    const int tid = threadIdx.x;
    const int c   = blockIdx.x * 128 + tid;    // channel in [0, 8192)
    const int s   = blockIdx.y;
    const int b   = blockIdx.z;
    const size_t rowbase = (size_t)(b * SS) * PDIM + c;

    float w0 = conv_w[c * 4 + 0], w1 = conv_w[c * 4 + 1];
    float w2 = conv_w[c * 4 + 2], w3 = conv_w[c * 4 + 3];

    float acc = w3 * g_qkvz[rowbase + (size_t)s * PDIM];
    if (s >= 1) acc = fmaf(w2, g_qkvz[rowbase + (size_t)(s - 1) * PDIM], acc);
    if (s >= 2) acc = fmaf(w1, g_qkvz[rowbase + (size_t)(s - 2) * PDIM], acc);
    if (s >= 3) acc = fmaf(w0, g_qkvz[rowbase + (size_t)(s - 3) * PDIM], acc);

    float val = acc / (1.f + expf(-acc));       // SiLU
    const size_t row = (size_t)b * SS + s;

    if (c < 2 * KEYD) {                          // q or k: l2norm over the head (this block)
        __shared__ float red[4];
        float ss = val * val;
#pragma unroll
        for (int off = 16; off; off >>= 1)
            ss += __shfl_xor_sync(0xFFFFFFFFu, ss, off);
        if ((tid & 31) == 0) red[tid >> 5] = ss;
        __syncthreads();
        float tot = red[0] + red[1] + red[2] + red[3];
        float rs  = rsqrtf(tot + 1e-6f);
        float o   = val * rs;
        if (c < KEYD) g_qn[row * KEYD + c]          = o;
        else          g_kn[row * KEYD + (c - KEYD)] = o;
    } else {
        g_v[row * VDIM + (c - 2 * KEYD)] = val;
    }
}

// =====================================================================
// beta = sigmoid(b); ge = exp(-exp(A_log)*softplus(a+dt_bias))
// =====================================================================
__global__ __launch_bounds__(256) void gate_prep(
    const float* __restrict__ dt_bias, const float* __restrict__ A_log)
{
    const int idx = blockIdx.x * 256 + threadIdx.x;   // ROWS*NVH = 131072
    const int row = idx >> 5, h = idx & 31;
    float bv = g_ba[row * 64 + h];
    float av = g_ba[row * 64 + 32 + h];
    float beta = 1.f / (1.f + expf(-bv));
    float xx = av + dt_bias[h];
    float sp = xx > 20.f ? xx : log1pf(expf(xx));
    float g  = -expf(A_log[h]) * sp;
    g_beta[row * NVH + h] = beta;
    g_ge[row * NVH + h]   = expf(g);
}

// =====================================================================
// Gated delta-rule scan. 128 CTAs = (b, h, v-half). 256 threads.
// tid = vloc*4 + ksec : thread owns k-slice [ksec*32, +32) of column vloc.
// State column slice lives in registers; k/q broadcast via padded smem.
// =====================================================================
__global__ __launch_bounds__(256, 1) void scan_kernel()
{
    __shared__ float k_sm[2][144];   // 4 groups * 36 (pad: conflict-free)
    __shared__ float q_sm[2][144];
    __shared__ float v_sm[2][64];
    __shared__ float sc_sm[2][2];

    const int bx   = blockIdx.x;
    const int b    = bx >> 6;
    const int h    = (bx >> 1) & 31;
    const int half = bx & 1;
    const int kh   = h >> 1;                 // GQA: rep=2
    const int tid  = threadIdx.x;
    const int vloc = tid >> 2;
    const int ks   = tid & 3;

    float s[32];
#pragma unroll
    for (int i = 0; i < 32; i++) s[i] = 0.f;

    // staged load registers
    float4 lk = {0, 0, 0, 0}, lq = {0, 0, 0, 0}, lv = {0, 0, 0, 0};
    float  lsc = 0.f;

    // prologue: load t = 0
    {
        const size_t row = (size_t)b * SS;
        if (tid < 32)       lk = *(const float4*)(g_kn + row * KEYD + kh * 128 + tid * 4);
        else if (tid < 64)  lq = *(const float4*)(g_qn + row * KEYD + kh * 128 + (tid - 32) * 4);
        else if (tid < 80)  lv = *(const float4*)(g_v  + row * VDIM + h * 128 + half * 64 + (tid - 64) * 4);
        else if (tid == 80) lsc = g_ge[row * NVH + h];
        else if (tid == 81) lsc = g_beta[row * NVH + h];
    }

    for (int t = 0; t < SS; t++) {
        const int buf = t & 1;
        // stage into smem
        if (tid < 32) {
            *(float4*)&k_sm[buf][(tid >> 3) * 36 + ((tid * 4) & 31)] = lk;
        } else if (tid < 64) {
            const int t2 = tid - 32;
            *(float4*)&q_sm[buf][(t2 >> 3) * 36 + ((t2 * 4) & 31)] = lq;
        } else if (tid < 80) {
            *(float4*)&v_sm[buf][(tid - 64) * 4] = lv;
        } else if (tid == 80) sc_sm[buf][0] = lsc;
        else if (tid == 81)   sc_sm[buf][1] = lsc;

        // prefetch t+1
        if (t + 1 < SS) {
            const size_t row = (size_t)b * SS + (t + 1);
            if (tid < 32)       lk = *(const float4*)(g_kn + row * KEYD + kh * 128 + tid * 4);
            else if (tid < 64)  lq = *(const float4*)(g_qn + row * KEYD + kh * 128 + (tid - 32) * 4);
            else if (tid < 80)  lv = *(const float4*)(g_v  + row * VDIM + h * 128 + half * 64 + (tid - 64) * 4);
            else if (tid == 80) lsc = g_ge[row * NVH + h];
            else if (tid == 81) lsc = g_beta[row * NVH + h];
        }
        __syncthreads();

        const float g   = sc_sm[buf][0];
        const float bta = sc_sm[buf][1];
        const float vv  = v_sm[buf][vloc];
        const float* kp = &k_sm[buf][ks * 36];
        const float* qp = &q_sm[buf][ks * 36];

        float4 kk[8];
#pragma unroll
        for (int j = 0; j < 8; j++) kk[j] = *(const float4*)(kp + j * 4);

        // decay + k·state partial dot
        float a0 = 0.f, a1 = 0.f, a2 = 0.f, a3 = 0.f;
#pragma unroll
        for (int j = 0; j < 8; j++) {
            s[4 * j + 0] *= g; a0 = fmaf(kk[j].x, s[4 * j + 0], a0);
            s[4 * j + 1] *= g; a1 = fmaf(kk[j].y, s[4 * j + 1], a1);
            s[4 * j + 2] *= g; a2 = fmaf(kk[j].z, s[4 * j + 2], a2);
            s[4 * j + 3] *= g; a3 = fmaf(kk[j].w, s[4 * j + 3], a3);
        }
        float kv = (a0 + a1) + (a2 + a3);
        kv += __shfl_xor_sync(0xFFFFFFFFu, kv, 1);
        kv += __shfl_xor_sync(0xFFFFFFFFu, kv, 2);

        const float delta = bta * (vv - kv);

        // state update + q·state partial dot
        float o0 = 0.f, o1 = 0.f, o2 = 0.f, o3 = 0.f;
#pragma unroll
        for (int j = 0; j < 8; j++) {
            const float4 qq = *(const float4*)(qp + j * 4);
            s[4 * j + 0] = fmaf(kk[j].x, delta, s[4 * j + 0]); o0 = fmaf(qq.x, s[4 * j + 0], o0);
            s[4 * j + 1] = fmaf(kk[j].y, delta, s[4 * j + 1]); o1 = fmaf(qq.y, s[4 * j + 1], o1);
            s[4 * j + 2] = fmaf(kk[j].z, delta, s[4 * j + 2]); o2 = fmaf(qq.z, s[4 * j + 2], o2);
            s[4 * j + 3] = fmaf(kk[j].w, delta, s[4 * j + 3]); o3 = fmaf(qq.w, s[4 * j + 3], o3);
        }
        float o = (o0 + o1) + (o2 + o3);
        o += __shfl_xor_sync(0xFFFFFFFFu, o, 1);
        o += __shfl_xor_sync(0xFFFFFFFFu, o, 2);

        if (ks == 0)
            g_core[((size_t)b * SS + t) * VDIM + h * 128 + half * 64 + vloc] = o;
    }
}

// =====================================================================
// RMSNorm(core) * (1+norm_w) * SiLU(z) -> g_v (reused as gated buffer)
// one block per row, 256 threads
// =====================================================================
__global__ __launch_bounds__(256) void rms_gate(const float* __restrict__ norm_w)
{
    const int row = blockIdx.x;
    const int tid = threadIdx.x;
    float vals[16];
    float ss = 0.f;
#pragma unroll
    for (int i = 0; i < 16; i++) {
        float v = g_core[(size_t)row * VDIM + i * 256 + tid];
        vals[i] = v;
        ss = fmaf(v, v, ss);
    }
    __shared__ float red[8];
#pragma unroll
    for (int off = 16; off; off >>= 1)
        ss += __shfl_xor_sync(0xFFFFFFFFu, ss, off);
    if ((tid & 31) == 0) red[tid >> 5] = ss;
    __syncthreads();
    float tot = 0.f;
#pragma unroll
    for (int w = 0; w < 8; w++) tot += red[w];
    const float rs = rsqrtf(tot / (float)VDIM + 1e-6f);
#pragma unroll
    for (int i = 0; i < 16; i++) {
        const int c = i * 256 + tid;
        float z  = g_qkvz[(size_t)row * PDIM + 2 * KEYD + VDIM + c];
        float sz = z / (1.f + expf(-z));
        g_v[(size_t)row * VDIM + c] = vals[i] * rs * (1.f + norm_w[c]) * sz;
    }
}

// =====================================================================
extern "C" void kernel_launch(void* const* d_in, const int* in_sizes, int n_in,
                              void* d_out, int out_size)
{
    const float* x       = (const float*)d_in[0];
    const float* W_qkvz  = (const float*)d_in[1];
    const float* W_ba    = (const float*)d_in[2];
    const float* conv_w  = (const float*)d_in[3];
    const float* dt_bias = (const float*)d_in[4];
    const float* A_log   = (const float*)d_in[5];
    const float* norm_w  = (const float*)d_in[6];
    const float* W_out   = (const float*)d_in[7];
    float* out = (float*)d_out;

    float *p_qkvz, *p_gv;
    cudaGetSymbolAddress((void**)&p_qkvz, g_qkvz);
    cudaGetSymbolAddress((void**)&p_gv,   g_v);

    // 1) qkvz = x @ W_qkvz^T    [4096 x 12288]
    gemm_tf32<<<dim3(PDIM / 128, ROWS / 128), 256>>>(x, W_qkvz, p_qkvz, ROWS, PDIM, HID);
    // 2) ba = x @ W_ba^T        [4096 x 64]
    ba_gemm<<<ROWS * 64 / 8, 256>>>(x, W_ba);
    // 3) conv + silu + l2norm split
    conv_norm<<<dim3(64, SS, BB), 128>>>(conv_w);
    // 4) beta / exp(g)
    gate_prep<<<ROWS * NVH / 256, 256>>>(dt_bias, A_log);
    // 5) recurrent delta-rule scan
    scan_kernel<<<128, 256>>>();
    // 6) RMSNorm + (1+w) + silu(z) gate
    rms_gate<<<ROWS, 256>>>(norm_w);
    // 7) out = gated @ W_out^T  [4096 x 2048]
    gemm_tf32<<<dim3(HID / 128, ROWS / 128), 256>>>(p_gv, W_out, out, ROWS, HID, VDIM);
}

// round 6
// speedup vs baseline: 2.3783x; 2.3783x over previous
#include <cuda_runtime.h>
#include <cuda_fp16.h>
#include <cstdint>
#include <math.h>

// ---------------- problem dims ----------------
#define BB    2
#define SS    2048
#define HID   2048
#define VDIM  4096
#define KEYD  2048
#define NVH   32
#define ROWS  4096            // B*S
#define PD2   12416           // 12288 qkvz + 64 ba + 64 pad  (= 97*128)

// ---------------- static scratch ----------------
__device__ float  g_qkvz2[(size_t)ROWS * PD2];     // 203 MB, qkvz+ba fused output
__device__ float  g_qn  [(size_t)ROWS * KEYD];
__device__ float  g_kn  [(size_t)ROWS * KEYD];
__device__ float  g_v   [(size_t)ROWS * VDIM];
__device__ float  g_beta[ROWS * NVH];
__device__ float  g_ge  [ROWS * NVH];
__device__ float  g_core[(size_t)ROWS * VDIM];
__device__ __half g_xh  [(size_t)ROWS * HID];      // x in fp16
__device__ __half g_wh1 [(size_t)PD2 * HID];       // [W_qkvz; W_ba; 0] fp16
__device__ __half g_gh  [(size_t)ROWS * VDIM];     // gated core fp16
__device__ __half g_woh [(size_t)HID * VDIM];      // W_out fp16

// ---------------- helpers ----------------
__device__ __forceinline__ uint32_t smem_u32(const void* p) {
    uint32_t a;
    asm("{ .reg .u64 t; cvta.to.shared.u64 t, %1; cvt.u32.u64 %0, t; }" : "=r"(a) : "l"(p));
    return a;
}
#define SW128(o) ((o) ^ (((o) >> 3) & 0x70))

// f32x2 packed math (compiles on this target; verified R5 ptxas output)
__device__ __forceinline__ unsigned long long pk2(float lo, float hi) {
    unsigned long long r; asm("mov.b64 %0, {%1, %2};" : "=l"(r) : "f"(lo), "f"(hi)); return r;
}
__device__ __forceinline__ void upk2(unsigned long long v, float& lo, float& hi) {
    asm("mov.b64 {%0, %1}, %2;" : "=f"(lo), "=f"(hi) : "l"(v));
}
__device__ __forceinline__ unsigned long long f2mul(unsigned long long a, unsigned long long b) {
    unsigned long long d; asm("mul.rn.f32x2 %0, %1, %2;" : "=l"(d) : "l"(a), "l"(b)); return d;
}
__device__ __forceinline__ unsigned long long f2fma(unsigned long long a, unsigned long long b, unsigned long long c) {
    unsigned long long d; asm("fma.rn.f32x2 %0, %1, %2, %3;" : "=l"(d) : "l"(a), "l"(b), "l"(c)); return d;
}

// =====================================================================
// fp16 tensor-core GEMM: C[M,N] = A[M,K] * B[N,K]^T
// A,B fp16 row-major; C fp32. Tiles 128x128, K-stage 64, cp.async x3 stages,
// ldmatrix fragments, mma.m16n8k16. M%128==0, N%128==0, K%64==0.
// =====================================================================
#define BKH   64
#define STG_B 32768             // 16KB A + 16KB B per stage
#define GSMEM (3 * STG_B)       // 98304

__global__ __launch_bounds__(256) void gemm_f16(
    const __half* __restrict__ A, const __half* __restrict__ B,
    float* __restrict__ C, int M, int N, int K)
{
    extern __shared__ char sm[];
    const int tid  = threadIdx.x;
    const int warp = tid >> 5, lane = tid & 31;
    const int bm   = blockIdx.y * 128;
    const int bn   = blockIdx.x * 128;
    const int wm   = (warp & 1) * 64;
    const int wn   = (warp >> 1) * 32;

    const int lrow = tid >> 3;          // 0..31 base row for loads (x4 passes of 32? no: idx scheme below)
    (void)lrow;

    // ---- async stage loader: 128 rows x 128B each for A and B ----
    auto loadStage = [&](int st, int kt) {
        char* as = sm + st * STG_B;
        char* bs = as + 16384;
#pragma unroll
        for (int j = 0; j < 4; j++) {
            const int idx = tid + j * 256;       // 0..1023
            const int row = idx >> 3;            // 0..127
            const int c   = idx & 7;             // 16B chunk
            const uint32_t so = SW128((uint32_t)(row * 128 + c * 16));
            uint32_t da = smem_u32(as + so);
            const __half* sa = A + (size_t)(bm + row) * K + kt + c * 8;
            asm volatile("cp.async.cg.shared.global [%0], [%1], 16;" :: "r"(da), "l"(sa));
            uint32_t db = smem_u32(bs + so);
            const __half* sb = B + (size_t)(bn + row) * K + kt + c * 8;
            asm volatile("cp.async.cg.shared.global [%0], [%1], 16;" :: "r"(db), "l"(sb));
        }
        asm volatile("cp.async.commit_group;");
    };

    float acc[4][4][4];
#pragma unroll
    for (int i = 0; i < 4; i++)
#pragma unroll
        for (int j = 0; j < 4; j++)
#pragma unroll
            for (int r = 0; r < 4; r++) acc[i][j][r] = 0.f;

    const int S = K / BKH;
    loadStage(0, 0);
    loadStage(1, BKH);

    // per-lane ldmatrix address pieces
    const int aRowOff = (lane & 7) + ((lane >> 3) & 1) * 8;   // within m16
    const int aKOff   = (lane >> 4) * 16;                     // 0 or 16 bytes
    const int bRowOff = (lane & 7);
    const int bKOff   = (((lane & 15) >> 3)) * 16;

    for (int s = 0; s < S; s++) {
        if (s + 1 < S) asm volatile("cp.async.wait_group 1;" ::: "memory");
        else           asm volatile("cp.async.wait_group 0;" ::: "memory");
        __syncthreads();
        if (s + 2 < S) loadStage((s + 2) % 3, (s + 2) * BKH);

        const uint32_t aBase = smem_u32(sm + (s % 3) * STG_B);
        const uint32_t bBase = aBase + 16384;

#pragma unroll
        for (int kb = 0; kb < 4; kb++) {
            uint32_t af[4][4], bf[4][2];
#pragma unroll
            for (int i = 0; i < 4; i++) {
                const uint32_t ad = aBase +
                    SW128((uint32_t)((wm + i * 16 + aRowOff) * 128 + kb * 32 + aKOff));
                asm volatile("ldmatrix.sync.aligned.m8n8.x4.shared.b16 {%0,%1,%2,%3}, [%4];"
                    : "=r"(af[i][0]), "=r"(af[i][1]), "=r"(af[i][2]), "=r"(af[i][3]) : "r"(ad));
            }
#pragma unroll
            for (int j = 0; j < 4; j++) {
                const uint32_t bd = bBase +
                    SW128((uint32_t)((wn + j * 8 + bRowOff) * 128 + kb * 32 + bKOff));
                asm volatile("ldmatrix.sync.aligned.m8n8.x2.shared.b16 {%0,%1}, [%2];"
                    : "=r"(bf[j][0]), "=r"(bf[j][1]) : "r"(bd));
            }
#pragma unroll
            for (int i = 0; i < 4; i++)
#pragma unroll
                for (int j = 0; j < 4; j++)
                    asm volatile(
                        "mma.sync.aligned.m16n8k16.row.col.f32.f16.f16.f32 "
                        "{%0,%1,%2,%3}, {%4,%5,%6,%7}, {%8,%9}, {%0,%1,%2,%3};"
                        : "+f"(acc[i][j][0]), "+f"(acc[i][j][1]),
                          "+f"(acc[i][j][2]), "+f"(acc[i][j][3])
                        : "r"(af[i][0]), "r"(af[i][1]), "r"(af[i][2]), "r"(af[i][3]),
                          "r"(bf[j][0]), "r"(bf[j][1]));
        }
    }

#pragma unroll
    for (int i = 0; i < 4; i++)
#pragma unroll
        for (int j = 0; j < 4; j++) {
            const int r = bm + wm + i * 16 + (lane >> 2);
            const int c = bn + wn + j * 8 + (lane & 3) * 2;
            float2 v0; v0.x = acc[i][j][0]; v0.y = acc[i][j][1];
            float2 v1; v1.x = acc[i][j][2]; v1.y = acc[i][j][3];
            *(float2*)(C + (size_t)r * N + c)       = v0;
            *(float2*)(C + (size_t)(r + 8) * N + c) = v1;
        }
}

// =====================================================================
// conversions to fp16
// =====================================================================
__global__ __launch_bounds__(256) void cvt_x(const float* __restrict__ x)
{
    const size_t n = (size_t)ROWS * HID;
    for (size_t i = (size_t)blockIdx.x * 256 + threadIdx.x; i < n; i += (size_t)gridDim.x * 256)
        g_xh[i] = __float2half_rn(x[i]);
}
__global__ __launch_bounds__(256) void cvt_w1(
    const float* __restrict__ Wq, const float* __restrict__ Wb)
{
    const size_t n = (size_t)PD2 * HID;
    for (size_t i = (size_t)blockIdx.x * 256 + threadIdx.x; i < n; i += (size_t)gridDim.x * 256) {
        const int row = (int)(i >> 11);
        const int col = (int)(i & 2047);
        float v;
        if (row < 12288)      v = Wq[i];
        else if (row < 12352) v = Wb[(size_t)(row - 12288) * HID + col];
        else                  v = 0.f;
        g_wh1[i] = __float2half_rn(v);
    }
}
__global__ __launch_bounds__(256) void cvt_wo(const float* __restrict__ Wo)
{
    const size_t n = (size_t)HID * VDIM;
    for (size_t i = (size_t)blockIdx.x * 256 + threadIdx.x; i < n; i += (size_t)gridDim.x * 256)
        g_woh[i] = __float2half_rn(Wo[i]);
}

// =====================================================================
// Causal depthwise conv (K=4) + SiLU + split + l2norm(q,k per head)
// =====================================================================
__global__ __launch_bounds__(128) void conv_norm(const float* __restrict__ conv_w)
{
    const int tid = threadIdx.x;
    const int c   = blockIdx.x * 128 + tid;    // channel in [0, 8192)
    const int s   = blockIdx.y;
    const int b   = blockIdx.z;
    const size_t rowbase = (size_t)(b * SS) * PD2 + c;

    float w0 = conv_w[c * 4 + 0], w1 = conv_w[c * 4 + 1];
    float w2 = conv_w[c * 4 + 2], w3 = conv_w[c * 4 + 3];

    float acc = w3 * g_qkvz2[rowbase + (size_t)s * PD2];
    if (s >= 1) acc = fmaf(w2, g_qkvz2[rowbase + (size_t)(s - 1) * PD2], acc);
    if (s >= 2) acc = fmaf(w1, g_qkvz2[rowbase + (size_t)(s - 2) * PD2], acc);
    if (s >= 3) acc = fmaf(w0, g_qkvz2[rowbase + (size_t)(s - 3) * PD2], acc);

    float val = acc / (1.f + expf(-acc));
    const size_t row = (size_t)b * SS + s;

    if (c < 2 * KEYD) {
        __shared__ float red[4];
        float ss = val * val;
#pragma unroll
        for (int off = 16; off; off >>= 1)
            ss += __shfl_xor_sync(0xFFFFFFFFu, ss, off);
        if ((tid & 31) == 0) red[tid >> 5] = ss;
        __syncthreads();
        float tot = red[0] + red[1] + red[2] + red[3];
        float rs  = rsqrtf(tot + 1e-6f);
        float o   = val * rs;
        if (c < KEYD) g_qn[row * KEYD + c]          = o;
        else          g_kn[row * KEYD + (c - KEYD)] = o;
    } else {
        g_v[row * VDIM + (c - 2 * KEYD)] = val;
    }
}

// =====================================================================
// beta = sigmoid(b); ge = exp(-exp(A_log)*softplus(a+dt_bias))
// b,a live in g_qkvz2 cols [12288, 12352)
// =====================================================================
__global__ __launch_bounds__(256) void gate_prep(
    const float* __restrict__ dt_bias, const float* __restrict__ A_log)
{
    const int idx = blockIdx.x * 256 + threadIdx.x;
    const int row = idx >> 5, h = idx & 31;
    float bv = g_qkvz2[(size_t)row * PD2 + 12288 + h];
    float av = g_qkvz2[(size_t)row * PD2 + 12320 + h];
    float beta = 1.f / (1.f + expf(-bv));
    float xx = av + dt_bias[h];
    float sp = xx > 20.f ? xx : log1pf(expf(xx));
    float g  = -expf(A_log[h]) * sp;
    g_beta[row * NVH + h] = beta;
    g_ge[row * NVH + h]   = expf(g);
}

// =====================================================================
// Gated delta-rule scan, f32x2 packed. 128 CTAs = (b, h, v-half).
// =====================================================================
__global__ __launch_bounds__(256, 1) void scan_kernel()
{
    __shared__ __align__(16) float k_sm[2][144];
    __shared__ __align__(16) float q_sm[2][144];
    __shared__ float v_sm[2][64];
    __shared__ float sc_sm[2][2];

    const int bx   = blockIdx.x;
    const int b    = bx >> 6;
    const int h    = (bx >> 1) & 31;
    const int half = bx & 1;
    const int kh   = h >> 1;
    const int tid  = threadIdx.x;
    const int vloc = tid >> 2;
    const int ks   = tid & 3;

    unsigned long long sp[16];
#pragma unroll
    for (int i = 0; i < 16; i++) sp[i] = 0ull;

    float4 lk = {0,0,0,0}, lq = {0,0,0,0}, lv = {0,0,0,0};
    float  lsc = 0.f;
    {
        const size_t row = (size_t)b * SS;
        if (tid < 32)       lk = *(const float4*)(g_kn + row * KEYD + kh * 128 + tid * 4);
        else if (tid < 64)  lq = *(const float4*)(g_qn + row * KEYD + kh * 128 + (tid - 32) * 4);
        else if (tid < 80)  lv = *(const float4*)(g_v  + row * VDIM + h * 128 + half * 64 + (tid - 64) * 4);
        else if (tid == 80) lsc = g_ge[row * NVH + h];
        else if (tid == 81) lsc = g_beta[row * NVH + h];
    }

    for (int t = 0; t < SS; t++) {
        const int buf = t & 1;
        if (tid < 32) {
            *(float4*)&k_sm[buf][(tid >> 3) * 36 + ((tid * 4) & 31)] = lk;
        } else if (tid < 64) {
            const int t2 = tid - 32;
            *(float4*)&q_sm[buf][(t2 >> 3) * 36 + ((t2 * 4) & 31)] = lq;
        } else if (tid < 80) {
            *(float4*)&v_sm[buf][(tid - 64) * 4] = lv;
        } else if (tid == 80) sc_sm[buf][0] = lsc;
        else if (tid == 81)   sc_sm[buf][1] = lsc;

        if (t + 1 < SS) {
            const size_t row = (size_t)b * SS + (t + 1);
            if (tid < 32)       lk = *(const float4*)(g_kn + row * KEYD + kh * 128 + tid * 4);
            else if (tid < 64)  lq = *(const float4*)(g_qn + row * KEYD + kh * 128 + (tid - 32) * 4);
            else if (tid < 80)  lv = *(const float4*)(g_v  + row * VDIM + h * 128 + half * 64 + (tid - 64) * 4);
            else if (tid == 80) lsc = g_ge[row * NVH + h];
            else if (tid == 81) lsc = g_beta[row * NVH + h];
        }
        __syncthreads();

        const float g   = sc_sm[buf][0];
        const float bta = sc_sm[buf][1];
        const float vv  = v_sm[buf][vloc];
        const ulonglong2* kp2 = (const ulonglong2*)&k_sm[buf][ks * 36];
        const ulonglong2* qp2 = (const ulonglong2*)&q_sm[buf][ks * 36];

        unsigned long long kk[16];
#pragma unroll
        for (int j = 0; j < 8; j++) { ulonglong2 u = kp2[j]; kk[2*j] = u.x; kk[2*j+1] = u.y; }

        const unsigned long long gg = pk2(g, g);
        unsigned long long ac[4] = {0ull, 0ull, 0ull, 0ull};
#pragma unroll
        for (int j = 0; j < 16; j++) {
            sp[j] = f2mul(sp[j], gg);
            ac[j & 3] = f2fma(kk[j], sp[j], ac[j & 3]);
        }
        float kv, xl, xh;
        upk2(ac[0], xl, xh); kv = xl + xh;
        upk2(ac[1], xl, xh); kv += xl + xh;
        upk2(ac[2], xl, xh); kv += xl + xh;
        upk2(ac[3], xl, xh); kv += xl + xh;
        kv += __shfl_xor_sync(0xFFFFFFFFu, kv, 1);
        kv += __shfl_xor_sync(0xFFFFFFFFu, kv, 2);

        const float delta = bta * (vv - kv);
        const unsigned long long dd = pk2(delta, delta);

        unsigned long long qq[16];
#pragma unroll
        for (int j = 0; j < 8; j++) { ulonglong2 u = qp2[j]; qq[2*j] = u.x; qq[2*j+1] = u.y; }

        unsigned long long oc[4] = {0ull, 0ull, 0ull, 0ull};
#pragma unroll
        for (int j = 0; j < 16; j++) {
            sp[j] = f2fma(kk[j], dd, sp[j]);
            oc[j & 3] = f2fma(qq[j], sp[j], oc[j & 3]);
        }
        float o;
        upk2(oc[0], xl, xh); o = xl + xh;
        upk2(oc[1], xl, xh); o += xl + xh;
        upk2(oc[2], xl, xh); o += xl + xh;
        upk2(oc[3], xl, xh); o += xl + xh;
        o += __shfl_xor_sync(0xFFFFFFFFu, o, 1);
        o += __shfl_xor_sync(0xFFFFFFFFu, o, 2);

        if (ks == 0)
            g_core[((size_t)b * SS + t) * VDIM + h * 128 + half * 64 + vloc] = o;
    }
}

// =====================================================================
// RMSNorm(core) * (1+norm_w) * SiLU(z) -> g_gh (fp16)
// =====================================================================
__global__ __launch_bounds__(256) void rms_gate(const float* __restrict__ norm_w)
{
    const int row = blockIdx.x;
    const int tid = threadIdx.x;
    float vals[16];
    float ss = 0.f;
#pragma unroll
    for (int i = 0; i < 16; i++) {
        float v = g_core[(size_t)row * VDIM + i * 256 + tid];
        vals[i] = v;
        ss = fmaf(v, v, ss);
    }
    __shared__ float red[8];
#pragma unroll
    for (int off = 16; off; off >>= 1)
        ss += __shfl_xor_sync(0xFFFFFFFFu, ss, off);
    if ((tid & 31) == 0) red[tid >> 5] = ss;
    __syncthreads();
    float tot = 0.f;
#pragma unroll
    for (int w = 0; w < 8; w++) tot += red[w];
    const float rs = rsqrtf(tot / (float)VDIM + 1e-6f);
#pragma unroll
    for (int i = 0; i < 16; i++) {
        const int c = i * 256 + tid;
        float z  = g_qkvz2[(size_t)row * PD2 + 8192 + c];
        float sz = z / (1.f + expf(-z));
        g_gh[(size_t)row * VDIM + c] =
            __float2half_rn(vals[i] * rs * (1.f + norm_w[c]) * sz);
    }
}

// =====================================================================
extern "C" void kernel_launch(void* const* d_in, const int* in_sizes, int n_in,
                              void* d_out, int out_size)
{
    const float* x       = (const float*)d_in[0];
    const float* W_qkvz  = (const float*)d_in[1];
    const float* W_ba    = (const float*)d_in[2];
    const float* conv_w  = (const float*)d_in[3];
    const float* dt_bias = (const float*)d_in[4];
    const float* A_log   = (const float*)d_in[5];
    const float* norm_w  = (const float*)d_in[6];
    const float* W_out   = (const float*)d_in[7];
    float* out = (float*)d_out;

    float  *p_qkvz2;
    __half *p_xh, *p_wh1, *p_gh, *p_woh;
    cudaGetSymbolAddress((void**)&p_qkvz2, g_qkvz2);
    cudaGetSymbolAddress((void**)&p_xh,    g_xh);
    cudaGetSymbolAddress((void**)&p_wh1,   g_wh1);
    cudaGetSymbolAddress((void**)&p_gh,    g_gh);
    cudaGetSymbolAddress((void**)&p_woh,   g_woh);

    cudaFuncSetAttribute(gemm_f16, cudaFuncAttributeMaxDynamicSharedMemorySize, GSMEM);

    // 0) fp16 conversions (x, fused W1, W_out)
    cvt_x <<<2048, 256>>>(x);
    cvt_w1<<<4096, 256>>>(W_qkvz, W_ba);
    cvt_wo<<<2048, 256>>>(W_out);

    // 1) fused qkvz+ba GEMM: [4096 x 12416] = xh @ wh1^T
    gemm_f16<<<dim3(PD2 / 128, ROWS / 128), 256, GSMEM>>>(p_xh, p_wh1, p_qkvz2, ROWS, PD2, HID);

    // 2) conv + silu + l2norm split
    conv_norm<<<dim3(64, SS, BB), 128>>>(conv_w);
    // 3) beta / exp(g)
    gate_prep<<<ROWS * NVH / 256, 256>>>(dt_bias, A_log);
    // 4) recurrent delta-rule scan (f32x2)
    scan_kernel<<<128, 256>>>();
    // 5) RMSNorm + (1+w) + silu(z) gate -> fp16
    rms_gate<<<ROWS, 256>>>(norm_w);

    // 6) out = gated @ W_out^T  [4096 x 2048]
    gemm_f16<<<dim3(HID / 128, ROWS / 128), 256, GSMEM>>>(p_gh, p_woh, out, ROWS, HID, VDIM);
}

// round 7
// speedup vs baseline: 2.6057x; 1.0956x over previous
#include <cuda_runtime.h>
#include <cuda_fp16.h>
#include <cstdint>
#include <math.h>

// ---------------- problem dims ----------------
#define BB    2
#define SS    2048
#define HID   2048
#define VDIM  4096
#define KEYD  2048
#define NVH   32
#define ROWS  4096            // B*S
#define PD2   12416           // 12288 qkvz + 64 ba + 64 pad  (= 97*128)

// ---------------- static scratch ----------------
__device__ float  g_qkvz2[(size_t)ROWS * PD2];     // qkvz+ba fused output
__device__ float  g_qn  [(size_t)ROWS * KEYD];
__device__ float  g_kn  [(size_t)ROWS * KEYD];
__device__ float  g_v   [(size_t)ROWS * VDIM];
__device__ float  g_beta[ROWS * NVH];
__device__ float  g_ge  [ROWS * NVH];
__device__ float  g_core[(size_t)ROWS * VDIM];
__device__ __half g_xh  [(size_t)ROWS * HID];
__device__ __half g_wh1 [(size_t)PD2 * HID];
__device__ __half g_gh  [(size_t)ROWS * VDIM];
__device__ __half g_woh [(size_t)HID * VDIM];

// ---------------- helpers ----------------
__device__ __forceinline__ uint32_t smem_u32(const void* p) {
    uint32_t a;
    asm("{ .reg .u64 t; cvta.to.shared.u64 t, %1; cvt.u32.u64 %0, t; }" : "=r"(a) : "l"(p));
    return a;
}
#define SW128(o) ((o) ^ (((o) >> 3) & 0x70))

// f32x2 packed math
__device__ __forceinline__ unsigned long long pk2(float lo, float hi) {
    unsigned long long r; asm("mov.b64 %0, {%1, %2};" : "=l"(r) : "f"(lo), "f"(hi)); return r;
}
__device__ __forceinline__ void upk2(unsigned long long v, float& lo, float& hi) {
    asm("mov.b64 {%0, %1}, %2;" : "=f"(lo), "=f"(hi) : "l"(v));
}
__device__ __forceinline__ unsigned long long f2mul(unsigned long long a, unsigned long long b) {
    unsigned long long d; asm("mul.rn.f32x2 %0, %1, %2;" : "=l"(d) : "l"(a), "l"(b)); return d;
}
__device__ __forceinline__ unsigned long long f2fma(unsigned long long a, unsigned long long b, unsigned long long c) {
    unsigned long long d; asm("fma.rn.f32x2 %0, %1, %2, %3;" : "=l"(d) : "l"(a), "l"(b), "l"(c)); return d;
}

// =====================================================================
// fp16 tensor-core GEMM: C[M,N] = A[M,K] * B[N,K]^T
// 128x128 tile, K-stage 64, cp.async x3 stages, ldmatrix, mma.m16n8k16.
// 2 CTAs/SM (regs capped at 128) to fill sync bubbles.
// =====================================================================
#define BKH   64
#define STG_B 32768             // 16KB A + 16KB B per stage
#define GSMEM (3 * STG_B)       // 98304

__global__ __launch_bounds__(256, 2) void gemm_f16(
    const __half* __restrict__ A, const __half* __restrict__ B,
    float* __restrict__ C, int M, int N, int K)
{
    extern __shared__ char sm[];
    const int tid  = threadIdx.x;
    const int warp = tid >> 5, lane = tid & 31;
    const int bm   = blockIdx.y * 128;
    const int bn   = blockIdx.x * 128;
    const int wm   = (warp & 1) * 64;
    const int wn   = (warp >> 1) * 32;

    auto loadStage = [&](int st, int kt) {
        char* as = sm + st * STG_B;
        char* bs = as + 16384;
#pragma unroll
        for (int j = 0; j < 4; j++) {
            const int idx = tid + j * 256;
            const int row = idx >> 3;
            const int c   = idx & 7;
            const uint32_t so = SW128((uint32_t)(row * 128 + c * 16));
            uint32_t da = smem_u32(as + so);
            const __half* sa = A + (size_t)(bm + row) * K + kt + c * 8;
            asm volatile("cp.async.cg.shared.global [%0], [%1], 16;" :: "r"(da), "l"(sa));
            uint32_t db = smem_u32(bs + so);
            const __half* sb = B + (size_t)(bn + row) * K + kt + c * 8;
            asm volatile("cp.async.cg.shared.global [%0], [%1], 16;" :: "r"(db), "l"(sb));
        }
        asm volatile("cp.async.commit_group;");
    };

    float acc[4][4][4];
#pragma unroll
    for (int i = 0; i < 4; i++)
#pragma unroll
        for (int j = 0; j < 4; j++)
#pragma unroll
            for (int r = 0; r < 4; r++) acc[i][j][r] = 0.f;

    const int S = K / BKH;
    loadStage(0, 0);
    loadStage(1, BKH);

    // ldmatrix lane maps
    const int aRowOff = (lane & 7) + ((lane >> 3) & 1) * 8;
    const int aKOff   = (lane >> 4) * 16;
    const int bRow2   = (lane & 7) + ((lane >> 4) * 8);   // x4 pair map
    const int bK2     = ((lane >> 3) & 1) * 16;

    for (int s = 0; s < S; s++) {
        if (s + 1 < S) asm volatile("cp.async.wait_group 1;" ::: "memory");
        else           asm volatile("cp.async.wait_group 0;" ::: "memory");
        __syncthreads();
        if (s + 2 < S) loadStage((s + 2) % 3, (s + 2) * BKH);

        const uint32_t aBase = smem_u32(sm + (s % 3) * STG_B);
        const uint32_t bBase = aBase + 16384;

#pragma unroll
        for (int kb = 0; kb < 4; kb++) {
            uint32_t af[4][4], bf[2][4];
#pragma unroll
            for (int i = 0; i < 4; i++) {
                const uint32_t ad = aBase +
                    SW128((uint32_t)((wm + i * 16 + aRowOff) * 128 + kb * 32 + aKOff));
                asm volatile("ldmatrix.sync.aligned.m8n8.x4.shared.b16 {%0,%1,%2,%3}, [%4];"
                    : "=r"(af[i][0]), "=r"(af[i][1]), "=r"(af[i][2]), "=r"(af[i][3]) : "r"(ad));
            }
#pragma unroll
            for (int p = 0; p < 2; p++) {   // pair p covers tiles j=2p, 2p+1
                const uint32_t bd = bBase +
                    SW128((uint32_t)((wn + p * 16 + bRow2) * 128 + kb * 32 + bK2));
                asm volatile("ldmatrix.sync.aligned.m8n8.x4.shared.b16 {%0,%1,%2,%3}, [%4];"
                    : "=r"(bf[p][0]), "=r"(bf[p][1]), "=r"(bf[p][2]), "=r"(bf[p][3]) : "r"(bd));
            }
#pragma unroll
            for (int i = 0; i < 4; i++)
#pragma unroll
                for (int j = 0; j < 4; j++)
                    asm volatile(
                        "mma.sync.aligned.m16n8k16.row.col.f32.f16.f16.f32 "
                        "{%0,%1,%2,%3}, {%4,%5,%6,%7}, {%8,%9}, {%0,%1,%2,%3};"
                        : "+f"(acc[i][j][0]), "+f"(acc[i][j][1]),
                          "+f"(acc[i][j][2]), "+f"(acc[i][j][3])
                        : "r"(af[i][0]), "r"(af[i][1]), "r"(af[i][2]), "r"(af[i][3]),
                          "r"(bf[j >> 1][(j & 1) * 2]), "r"(bf[j >> 1][(j & 1) * 2 + 1]));
        }
    }

#pragma unroll
    for (int i = 0; i < 4; i++)
#pragma unroll
        for (int j = 0; j < 4; j++) {
            const int r = bm + wm + i * 16 + (lane >> 2);
            const int c = bn + wn + j * 8 + (lane & 3) * 2;
            float2 v0; v0.x = acc[i][j][0]; v0.y = acc[i][j][1];
            float2 v1; v1.x = acc[i][j][2]; v1.y = acc[i][j][3];
            *(float2*)(C + (size_t)r * N + c)       = v0;
            *(float2*)(C + (size_t)(r + 8) * N + c) = v1;
        }
}

// =====================================================================
// conversions to fp16
// =====================================================================
__global__ __launch_bounds__(256) void cvt_x(const float* __restrict__ x)
{
    const size_t n = (size_t)ROWS * HID;
    for (size_t i = (size_t)blockIdx.x * 256 + threadIdx.x; i < n; i += (size_t)gridDim.x * 256)
        g_xh[i] = __float2half_rn(x[i]);
}
__global__ __launch_bounds__(256) void cvt_w1(
    const float* __restrict__ Wq, const float* __restrict__ Wb)
{
    const size_t n = (size_t)PD2 * HID;
    for (size_t i = (size_t)blockIdx.x * 256 + threadIdx.x; i < n; i += (size_t)gridDim.x * 256) {
        const int row = (int)(i >> 11);
        const int col = (int)(i & 2047);
        float v;
        if (row < 12288)      v = Wq[i];
        else if (row < 12352) v = Wb[(size_t)(row - 12288) * HID + col];
        else                  v = 0.f;
        g_wh1[i] = __float2half_rn(v);
    }
}
__global__ __launch_bounds__(256) void cvt_wo(const float* __restrict__ Wo)
{
    const size_t n = (size_t)HID * VDIM;
    for (size_t i = (size_t)blockIdx.x * 256 + threadIdx.x; i < n; i += (size_t)gridDim.x * 256)
        g_woh[i] = __float2half_rn(Wo[i]);
}

// =====================================================================
// Sliding-window causal conv (K=4) + SiLU + l2norm split.
// grid (64 ch-blocks, 16 s-chunks, B). block 128 = one head's channels.
// Each CTA marches 128 s-steps keeping a 3-row register history.
// =====================================================================
#define SCHUNK 128

__global__ __launch_bounds__(128) void conv_norm(const float* __restrict__ conv_w)
{
    const int tid = threadIdx.x;
    const int c   = blockIdx.x * 128 + tid;       // channel 0..8191
    const int s0  = blockIdx.y * SCHUNK;
    const int b   = blockIdx.z;
    const bool isqk = (blockIdx.x < 32);

    __shared__ float red[2][4];

    const float w0 = conv_w[c * 4 + 0], w1 = conv_w[c * 4 + 1];
    const float w2 = conv_w[c * 4 + 2], w3 = conv_w[c * 4 + 3];

    const float* src = g_qkvz2 + (size_t)(b * SS) * PD2 + c;

    float xm3 = (s0 >= 3) ? src[(size_t)(s0 - 3) * PD2] : 0.f;
    float xm2 = (s0 >= 2) ? src[(size_t)(s0 - 2) * PD2] : 0.f;
    float xm1 = (s0 >= 1) ? src[(size_t)(s0 - 1) * PD2] : 0.f;
    float cur = src[(size_t)s0 * PD2];

    for (int i = 0; i < SCHUNK; i++) {
        const int s = s0 + i;
        float nxt = 0.f;
        if (i + 1 < SCHUNK) nxt = src[(size_t)(s + 1) * PD2];

        float acc = w3 * cur;
        acc = fmaf(w2, xm1, acc);
        acc = fmaf(w1, xm2, acc);
        acc = fmaf(w0, xm3, acc);
        xm3 = xm2; xm2 = xm1; xm1 = cur; cur = nxt;

        const float val = acc / (1.f + expf(-acc));
        const size_t row = (size_t)b * SS + s;

        if (isqk) {
            float ss = val * val;
#pragma unroll
            for (int off = 16; off; off >>= 1)
                ss += __shfl_xor_sync(0xFFFFFFFFu, ss, off);
            if ((tid & 31) == 0) red[i & 1][tid >> 5] = ss;
            __syncthreads();
            const float tot = red[i & 1][0] + red[i & 1][1] + red[i & 1][2] + red[i & 1][3];
            const float o = val * rsqrtf(tot + 1e-6f);
            if (c < KEYD) g_qn[row * KEYD + c]          = o;
            else          g_kn[row * KEYD + (c - KEYD)] = o;
        } else {
            g_v[row * VDIM + (c - 2 * KEYD)] = val;
        }
    }
}

// =====================================================================
// beta = sigmoid(b); ge = exp(-exp(A_log)*softplus(a+dt_bias))
// =====================================================================
__global__ __launch_bounds__(256) void gate_prep(
    const float* __restrict__ dt_bias, const float* __restrict__ A_log)
{
    const int idx = blockIdx.x * 256 + threadIdx.x;
    const int row = idx >> 5, h = idx & 31;
    float bv = g_qkvz2[(size_t)row * PD2 + 12288 + h];
    float av = g_qkvz2[(size_t)row * PD2 + 12320 + h];
    float beta = 1.f / (1.f + expf(-bv));
    float xx = av + dt_bias[h];
    float sp = xx > 20.f ? xx : log1pf(expf(xx));
    float g  = -expf(A_log[h]) * sp;
    g_beta[row * NVH + h] = beta;
    g_ge[row * NVH + h]   = expf(g);
}

// =====================================================================
// Gated delta-rule scan, f32x2 packed. 128 CTAs = (b, h, v-half).
// =====================================================================
__global__ __launch_bounds__(256, 1) void scan_kernel()
{
    __shared__ __align__(16) float k_sm[2][144];
    __shared__ __align__(16) float q_sm[2][144];
    __shared__ float v_sm[2][64];
    __shared__ float sc_sm[2][2];

    const int bx   = blockIdx.x;
    const int b    = bx >> 6;
    const int h    = (bx >> 1) & 31;
    const int half = bx & 1;
    const int kh   = h >> 1;
    const int tid  = threadIdx.x;
    const int vloc = tid >> 2;
    const int ks   = tid & 3;

    unsigned long long sp[16];
#pragma unroll
    for (int i = 0; i < 16; i++) sp[i] = 0ull;

    float4 lk = {0,0,0,0}, lq = {0,0,0,0}, lv = {0,0,0,0};
    float  lsc = 0.f;
    {
        const size_t row = (size_t)b * SS;
        if (tid < 32)       lk = *(const float4*)(g_kn + row * KEYD + kh * 128 + tid * 4);
        else if (tid < 64)  lq = *(const float4*)(g_qn + row * KEYD + kh * 128 + (tid - 32) * 4);
        else if (tid < 80)  lv = *(const float4*)(g_v  + row * VDIM + h * 128 + half * 64 + (tid - 64) * 4);
        else if (tid == 80) lsc = g_ge[row * NVH + h];
        else if (tid == 81) lsc = g_beta[row * NVH + h];
    }

    for (int t = 0; t < SS; t++) {
        const int buf = t & 1;
        if (tid < 32) {
            *(float4*)&k_sm[buf][(tid >> 3) * 36 + ((tid * 4) & 31)] = lk;
        } else if (tid < 64) {
            const int t2 = tid - 32;
            *(float4*)&q_sm[buf][(t2 >> 3) * 36 + ((t2 * 4) & 31)] = lq;
        } else if (tid < 80) {
            *(float4*)&v_sm[buf][(tid - 64) * 4] = lv;
        } else if (tid == 80) sc_sm[buf][0] = lsc;
        else if (tid == 81)   sc_sm[buf][1] = lsc;

        if (t + 1 < SS) {
            const size_t row = (size_t)b * SS + (t + 1);
            if (tid < 32)       lk = *(const float4*)(g_kn + row * KEYD + kh * 128 + tid * 4);
            else if (tid < 64)  lq = *(const float4*)(g_qn + row * KEYD + kh * 128 + (tid - 32) * 4);
            else if (tid < 80)  lv = *(const float4*)(g_v  + row * VDIM + h * 128 + half * 64 + (tid - 64) * 4);
            else if (tid == 80) lsc = g_ge[row * NVH + h];
            else if (tid == 81) lsc = g_beta[row * NVH + h];
        }
        __syncthreads();

        const float g   = sc_sm[buf][0];
        const float bta = sc_sm[buf][1];
        const float vv  = v_sm[buf][vloc];
        const ulonglong2* kp2 = (const ulonglong2*)&k_sm[buf][ks * 36];
        const ulonglong2* qp2 = (const ulonglong2*)&q_sm[buf][ks * 36];

        unsigned long long kk[16];
#pragma unroll
        for (int j = 0; j < 8; j++) { ulonglong2 u = kp2[j]; kk[2*j] = u.x; kk[2*j+1] = u.y; }

        const unsigned long long gg = pk2(g, g);
        unsigned long long ac[4] = {0ull, 0ull, 0ull, 0ull};
#pragma unroll
        for (int j = 0; j < 16; j++) {
            sp[j] = f2mul(sp[j], gg);
            ac[j & 3] = f2fma(kk[j], sp[j], ac[j & 3]);
        }
        float kv, xl, xh;
        upk2(ac[0], xl, xh); kv = xl + xh;
        upk2(ac[1], xl, xh); kv += xl + xh;
        upk2(ac[2], xl, xh); kv += xl + xh;
        upk2(ac[3], xl, xh); kv += xl + xh;
        kv += __shfl_xor_sync(0xFFFFFFFFu, kv, 1);
        kv += __shfl_xor_sync(0xFFFFFFFFu, kv, 2);

        const float delta = bta * (vv - kv);
        const unsigned long long dd = pk2(delta, delta);

        unsigned long long qq[16];
#pragma unroll
        for (int j = 0; j < 8; j++) { ulonglong2 u = qp2[j]; qq[2*j] = u.x; qq[2*j+1] = u.y; }

        unsigned long long oc[4] = {0ull, 0ull, 0ull, 0ull};
#pragma unroll
        for (int j = 0; j < 16; j++) {
            sp[j] = f2fma(kk[j], dd, sp[j]);
            oc[j & 3] = f2fma(qq[j], sp[j], oc[j & 3]);
        }
        float o;
        upk2(oc[0], xl, xh); o = xl + xh;
        upk2(oc[1], xl, xh); o += xl + xh;
        upk2(oc[2], xl, xh); o += xl + xh;
        upk2(oc[3], xl, xh); o += xl + xh;
        o += __shfl_xor_sync(0xFFFFFFFFu, o, 1);
        o += __shfl_xor_sync(0xFFFFFFFFu, o, 2);

        if (ks == 0)
            g_core[((size_t)b * SS + t) * VDIM + h * 128 + half * 64 + vloc] = o;
    }
}

// =====================================================================
// RMSNorm(core) * (1+norm_w) * SiLU(z) -> g_gh (fp16)
// =====================================================================
__global__ __launch_bounds__(256) void rms_gate(const float* __restrict__ norm_w)
{
    const int row = blockIdx.x;
    const int tid = threadIdx.x;
    float vals[16];
    float ss = 0.f;
#pragma unroll
    for (int i = 0; i < 16; i++) {
        float v = g_core[(size_t)row * VDIM + i * 256 + tid];
        vals[i] = v;
        ss = fmaf(v, v, ss);
    }
    __shared__ float red[8];
#pragma unroll
    for (int off = 16; off; off >>= 1)
        ss += __shfl_xor_sync(0xFFFFFFFFu, ss, off);
    if ((tid & 31) == 0) red[tid >> 5] = ss;
    __syncthreads();
    float tot = 0.f;
#pragma unroll
    for (int w = 0; w < 8; w++) tot += red[w];
    const float rs = rsqrtf(tot / (float)VDIM + 1e-6f);
#pragma unroll
    for (int i = 0; i < 16; i++) {
        const int c = i * 256 + tid;
        float z  = g_qkvz2[(size_t)row * PD2 + 8192 + c];
        float sz = z / (1.f + expf(-z));
        g_gh[(size_t)row * VDIM + c] =
            __float2half_rn(vals[i] * rs * (1.f + norm_w[c]) * sz);
    }
}

// =====================================================================
extern "C" void kernel_launch(void* const* d_in, const int* in_sizes, int n_in,
                              void* d_out, int out_size)
{
    const float* x       = (const float*)d_in[0];
    const float* W_qkvz  = (const float*)d_in[1];
    const float* W_ba    = (const float*)d_in[2];
    const float* conv_w  = (const float*)d_in[3];
    const float* dt_bias = (const float*)d_in[4];
    const float* A_log   = (const float*)d_in[5];
    const float* norm_w  = (const float*)d_in[6];
    const float* W_out   = (const float*)d_in[7];
    float* out = (float*)d_out;

    float  *p_qkvz2;
    __half *p_xh, *p_wh1, *p_gh, *p_woh;
    cudaGetSymbolAddress((void**)&p_qkvz2, g_qkvz2);
    cudaGetSymbolAddress((void**)&p_xh,    g_xh);
    cudaGetSymbolAddress((void**)&p_wh1,   g_wh1);
    cudaGetSymbolAddress((void**)&p_gh,    g_gh);
    cudaGetSymbolAddress((void**)&p_woh,   g_woh);

    cudaFuncSetAttribute(gemm_f16, cudaFuncAttributeMaxDynamicSharedMemorySize, GSMEM);

    // 0) fp16 conversions
    cvt_x <<<2048, 256>>>(x);
    cvt_w1<<<4096, 256>>>(W_qkvz, W_ba);
    cvt_wo<<<2048, 256>>>(W_out);

    // 1) fused qkvz+ba GEMM
    gemm_f16<<<dim3(PD2 / 128, ROWS / 128), 256, GSMEM>>>(p_xh, p_wh1, p_qkvz2, ROWS, PD2, HID);

    // 2) conv + silu + l2norm split (sliding window)
    conv_norm<<<dim3(64, SS / SCHUNK, BB), 128>>>(conv_w);
    // 3) beta / exp(g)
    gate_prep<<<ROWS * NVH / 256, 256>>>(dt_bias, A_log);
    // 4) recurrent delta-rule scan
    scan_kernel<<<128, 256>>>();
    // 5) RMSNorm + gate -> fp16
    rms_gate<<<ROWS, 256>>>(norm_w);
    // 6) out = gated @ W_out^T
    gemm_f16<<<dim3(HID / 128, ROWS / 128), 256, GSMEM>>>(p_gh, p_woh, out, ROWS, HID, VDIM);
}

// round 9
// speedup vs baseline: 3.6111x; 1.3859x over previous
#include <cuda_runtime.h>
#include <cuda_fp16.h>
#include <cstdint>
#include <math.h>

// ---------------- problem dims ----------------
#define BB    2
#define SS    2048
#define HID   2048
#define VDIM  4096
#define KEYD  2048
#define NVH   32
#define ROWS  4096            // B*S
#define PD2   12416           // 12288 qkvz + 64 ba + 64 pad  (= 97*128)

// ---------------- static scratch ----------------
__device__ __half g_qkvz2[(size_t)ROWS * PD2];     // fp16 qkvz+ba fused output
__device__ float  g_qn  [(size_t)ROWS * KEYD];
__device__ float  g_kn  [(size_t)ROWS * KEYD];
__device__ float  g_v   [(size_t)ROWS * VDIM];
__device__ float  g_beta[ROWS * NVH];
__device__ float  g_ge  [ROWS * NVH];
__device__ float  g_core[(size_t)ROWS * VDIM];
__device__ __half g_xh  [(size_t)ROWS * HID];
__device__ __half g_wh1 [(size_t)PD2 * HID];
__device__ __half g_gh  [(size_t)ROWS * VDIM];
__device__ __half g_woh [(size_t)HID * VDIM];

// ---------------- helpers ----------------
__device__ __forceinline__ uint32_t smem_u32(const void* p) {
    uint32_t a;
    asm("{ .reg .u64 t; cvta.to.shared.u64 t, %1; cvt.u32.u64 %0, t; }" : "=r"(a) : "l"(p));
    return a;
}
#define SW128(o) ((o) ^ (((o) >> 3) & 0x70))

// f32x2 packed math
__device__ __forceinline__ unsigned long long pk2(float lo, float hi) {
    unsigned long long r; asm("mov.b64 %0, {%1, %2};" : "=l"(r) : "f"(lo), "f"(hi)); return r;
}
__device__ __forceinline__ void upk2(unsigned long long v, float& lo, float& hi) {
    asm("mov.b64 {%0, %1}, %2;" : "=f"(lo), "=f"(hi) : "l"(v));
}
__device__ __forceinline__ unsigned long long f2mul(unsigned long long a, unsigned long long b) {
    unsigned long long d; asm("mul.rn.f32x2 %0, %1, %2;" : "=l"(d) : "l"(a), "l"(b)); return d;
}
__device__ __forceinline__ unsigned long long f2fma(unsigned long long a, unsigned long long b, unsigned long long c) {
    unsigned long long d; asm("fma.rn.f32x2 %0, %1, %2, %3;" : "=l"(d) : "l"(a), "l"(b), "l"(c)); return d;
}

// =====================================================================
// fp16 tensor-core GEMM: C[M,N] = A[M,K] * B[N,K]^T
// 128x128 tile, K-stage 64, cp.async x3 stages, ldmatrix, mma.m16n8k16.
// OutT = __half or float.
// =====================================================================
#define BKH   64
#define STG_B 32768
#define GSMEM (3 * STG_B)

template <typename OutT>
__global__ __launch_bounds__(256, 2) void gemm_f16(
    const __half* __restrict__ A, const __half* __restrict__ B,
    OutT* __restrict__ C, int M, int N, int K)
{
    extern __shared__ char sm[];
    const int tid  = threadIdx.x;
    const int warp = tid >> 5, lane = tid & 31;
    const int bm   = blockIdx.y * 128;
    const int bn   = blockIdx.x * 128;
    const int wm   = (warp & 1) * 64;
    const int wn   = (warp >> 1) * 32;

    auto loadStage = [&](int st, int kt) {
        char* as = sm + st * STG_B;
        char* bs = as + 16384;
#pragma unroll
        for (int j = 0; j < 4; j++) {
            const int idx = tid + j * 256;
            const int row = idx >> 3;
            const int c   = idx & 7;
            const uint32_t so = SW128((uint32_t)(row * 128 + c * 16));
            uint32_t da = smem_u32(as + so);
            const __half* sa = A + (size_t)(bm + row) * K + kt + c * 8;
            asm volatile("cp.async.cg.shared.global [%0], [%1], 16;" :: "r"(da), "l"(sa));
            uint32_t db = smem_u32(bs + so);
            const __half* sb = B + (size_t)(bn + row) * K + kt + c * 8;
            asm volatile("cp.async.cg.shared.global [%0], [%1], 16;" :: "r"(db), "l"(sb));
        }
        asm volatile("cp.async.commit_group;");
    };

    float acc[4][4][4];
#pragma unroll
    for (int i = 0; i < 4; i++)
#pragma unroll
        for (int j = 0; j < 4; j++)
#pragma unroll
            for (int r = 0; r < 4; r++) acc[i][j][r] = 0.f;

    const int S = K / BKH;
    loadStage(0, 0);
    loadStage(1, BKH);

    const int aRowOff = (lane & 7) + ((lane >> 3) & 1) * 8;
    const int aKOff   = (lane >> 4) * 16;
    const int bRow2   = (lane & 7) + ((lane >> 4) * 8);
    const int bK2     = ((lane >> 3) & 1) * 16;

    for (int s = 0; s < S; s++) {
        if (s + 1 < S) asm volatile("cp.async.wait_group 1;" ::: "memory");
        else           asm volatile("cp.async.wait_group 0;" ::: "memory");
        __syncthreads();
        if (s + 2 < S) loadStage((s + 2) % 3, (s + 2) * BKH);

        const uint32_t aBase = smem_u32(sm + (s % 3) * STG_B);
        const uint32_t bBase = aBase + 16384;

#pragma unroll
        for (int kb = 0; kb < 4; kb++) {
            uint32_t af[4][4], bf[2][4];
#pragma unroll
            for (int i = 0; i < 4; i++) {
                const uint32_t ad = aBase +
                    SW128((uint32_t)((wm + i * 16 + aRowOff) * 128 + kb * 32 + aKOff));
                asm volatile("ldmatrix.sync.aligned.m8n8.x4.shared.b16 {%0,%1,%2,%3}, [%4];"
                    : "=r"(af[i][0]), "=r"(af[i][1]), "=r"(af[i][2]), "=r"(af[i][3]) : "r"(ad));
            }
#pragma unroll
            for (int p = 0; p < 2; p++) {
                const uint32_t bd = bBase +
                    SW128((uint32_t)((wn + p * 16 + bRow2) * 128 + kb * 32 + bK2));
                asm volatile("ldmatrix.sync.aligned.m8n8.x4.shared.b16 {%0,%1,%2,%3}, [%4];"
                    : "=r"(bf[p][0]), "=r"(bf[p][1]), "=r"(bf[p][2]), "=r"(bf[p][3]) : "r"(bd));
            }
#pragma unroll
            for (int i = 0; i < 4; i++)
#pragma unroll
                for (int j = 0; j < 4; j++)
                    asm volatile(
                        "mma.sync.aligned.m16n8k16.row.col.f32.f16.f16.f32 "
                        "{%0,%1,%2,%3}, {%4,%5,%6,%7}, {%8,%9}, {%0,%1,%2,%3};"
                        : "+f"(acc[i][j][0]), "+f"(acc[i][j][1]),
                          "+f"(acc[i][j][2]), "+f"(acc[i][j][3])
                        : "r"(af[i][0]), "r"(af[i][1]), "r"(af[i][2]), "r"(af[i][3]),
                          "r"(bf[j >> 1][(j & 1) * 2]), "r"(bf[j >> 1][(j & 1) * 2 + 1]));
        }
    }

#pragma unroll
    for (int i = 0; i < 4; i++)
#pragma unroll
        for (int j = 0; j < 4; j++) {
            const int r = bm + wm + i * 16 + (lane >> 2);
            const int c = bn + wn + j * 8 + (lane & 3) * 2;
            if (sizeof(OutT) == 2) {
                __half2* d0 = (__half2*)((__half*)C + (size_t)r * N + c);
                __half2* d1 = (__half2*)((__half*)C + (size_t)(r + 8) * N + c);
                *d0 = __floats2half2_rn(acc[i][j][0], acc[i][j][1]);
                *d1 = __floats2half2_rn(acc[i][j][2], acc[i][j][3]);
            } else {
                float2 v0; v0.x = acc[i][j][0]; v0.y = acc[i][j][1];
                float2 v1; v1.x = acc[i][j][2]; v1.y = acc[i][j][3];
                *(float2*)((float*)C + (size_t)r * N + c)       = v0;
                *(float2*)((float*)C + (size_t)(r + 8) * N + c) = v1;
            }
        }
}

// =====================================================================
// conversions to fp16
// =====================================================================
__global__ __launch_bounds__(256) void cvt_x(const float* __restrict__ x)
{
    const size_t n = (size_t)ROWS * HID;
    for (size_t i = (size_t)blockIdx.x * 256 + threadIdx.x; i < n; i += (size_t)gridDim.x * 256)
        g_xh[i] = __float2half_rn(x[i]);
}
__global__ __launch_bounds__(256) void cvt_w1(
    const float* __restrict__ Wq, const float* __restrict__ Wb)
{
    const size_t n = (size_t)PD2 * HID;
    for (size_t i = (size_t)blockIdx.x * 256 + threadIdx.x; i < n; i += (size_t)gridDim.x * 256) {
        const int row = (int)(i >> 11);
        const int col = (int)(i & 2047);
        float v;
        if (row < 12288)      v = Wq[i];
        else if (row < 12352) v = Wb[(size_t)(row - 12288) * HID + col];
        else                  v = 0.f;
        g_wh1[i] = __float2half_rn(v);
    }
}
__global__ __launch_bounds__(256) void cvt_wo(const float* __restrict__ Wo)
{
    const size_t n = (size_t)HID * VDIM;
    for (size_t i = (size_t)blockIdx.x * 256 + threadIdx.x; i < n; i += (size_t)gridDim.x * 256)
        g_woh[i] = __float2half_rn(Wo[i]);
}

// =====================================================================
// Sliding-window causal conv (K=4) + SiLU + l2norm split (fp16 input)
// =====================================================================
#define SCHUNK 128

__global__ __launch_bounds__(128) void conv_norm(const float* __restrict__ conv_w)
{
    const int tid = threadIdx.x;
    const int c   = blockIdx.x * 128 + tid;
    const int s0  = blockIdx.y * SCHUNK;
    const int b   = blockIdx.z;
    const bool isqk = (blockIdx.x < 32);

    __shared__ float red[2][4];

    const float w0 = conv_w[c * 4 + 0], w1 = conv_w[c * 4 + 1];
    const float w2 = conv_w[c * 4 + 2], w3 = conv_w[c * 4 + 3];

    const __half* src = g_qkvz2 + (size_t)(b * SS) * PD2 + c;

    float xm3 = (s0 >= 3) ? __half2float(src[(size_t)(s0 - 3) * PD2]) : 0.f;
    float xm2 = (s0 >= 2) ? __half2float(src[(size_t)(s0 - 2) * PD2]) : 0.f;
    float xm1 = (s0 >= 1) ? __half2float(src[(size_t)(s0 - 1) * PD2]) : 0.f;
    float cur = __half2float(src[(size_t)s0 * PD2]);

    for (int i = 0; i < SCHUNK; i++) {
        const int s = s0 + i;
        float nxt = 0.f;
        if (i + 1 < SCHUNK) nxt = __half2float(src[(size_t)(s + 1) * PD2]);

        float acc = w3 * cur;
        acc = fmaf(w2, xm1, acc);
        acc = fmaf(w1, xm2, acc);
        acc = fmaf(w0, xm3, acc);
        xm3 = xm2; xm2 = xm1; xm1 = cur; cur = nxt;

        const float val = acc / (1.f + expf(-acc));
        const size_t row = (size_t)b * SS + s;

        if (isqk) {
            float ss = val * val;
#pragma unroll
            for (int off = 16; off; off >>= 1)
                ss += __shfl_xor_sync(0xFFFFFFFFu, ss, off);
            if ((tid & 31) == 0) red[i & 1][tid >> 5] = ss;
            __syncthreads();
            const float tot = red[i & 1][0] + red[i & 1][1] + red[i & 1][2] + red[i & 1][3];
            const float o = val * rsqrtf(tot + 1e-6f);
            if (c < KEYD) g_qn[row * KEYD + c]          = o;
            else          g_kn[row * KEYD + (c - KEYD)] = o;
        } else {
            g_v[row * VDIM + (c - 2 * KEYD)] = val;
        }
    }
}

// =====================================================================
// beta = sigmoid(b); ge = exp(-exp(A_log)*softplus(a+dt_bias))
// =====================================================================
__global__ __launch_bounds__(256) void gate_prep(
    const float* __restrict__ dt_bias, const float* __restrict__ A_log)
{
    const int idx = blockIdx.x * 256 + threadIdx.x;
    const int row = idx >> 5, h = idx & 31;
    float bv = __half2float(g_qkvz2[(size_t)row * PD2 + 12288 + h]);
    float av = __half2float(g_qkvz2[(size_t)row * PD2 + 12320 + h]);
    float beta = 1.f / (1.f + expf(-bv));
    float xx = av + dt_bias[h];
    float sp = xx > 20.f ? xx : log1pf(expf(xx));
    float g  = -expf(A_log[h]) * sp;
    g_beta[row * NVH + h] = beta;
    g_ge[row * NVH + h]   = expf(g);
}

// =====================================================================
// Gated delta-rule scan, f32x2. 256 CTAs = (b, h, quarter). 128 threads.
// Two time steps per barrier. Decay reordered: kv = g * dot(k, s_old).
// =====================================================================
__global__ __launch_bounds__(128, 2) void scan_kernel()
{
    __shared__ __align__(16) float k_sm[2][2][144];
    __shared__ __align__(16) float q_sm[2][2][144];
    __shared__ float v_sm[2][2][32];
    __shared__ float sc_sm[2][2][2];

    const int bx  = blockIdx.x;          // 0..255
    const int b   = bx >> 7;
    const int h   = (bx >> 2) & 31;
    const int qt  = bx & 3;
    const int kh  = h >> 1;
    const int tid = threadIdx.x;
    const int vloc = tid >> 2;           // 0..31
    const int ks   = tid & 3;

    unsigned long long sp[16];
#pragma unroll
    for (int i = 0; i < 16; i++) sp[i] = 0ull;

    float4 lkq = {0,0,0,0}, lv = {0,0,0,0};
    float  lsc = 0.f;

    auto prefetch = [&](int t) {
        const size_t rb = (size_t)b * SS;
        if (tid < 64) {
            const int st = tid >> 5, idx = tid & 31;
            lkq = *(const float4*)(g_kn + (rb + t + st) * KEYD + kh * 128 + idx * 4);
        } else {
            const int t2 = tid - 64, st = t2 >> 5, idx = t2 & 31;
            lkq = *(const float4*)(g_qn + (rb + t + st) * KEYD + kh * 128 + idx * 4);
        }
        if (tid < 16) {
            const int st = tid >> 3, idx = tid & 7;
            lv = *(const float4*)(g_v + (rb + t + st) * VDIM + h * 128 + qt * 32 + idx * 4);
        } else if (tid < 20) {
            const int w = tid - 16;
            const size_t rr = rb + t + (w >> 1);
            lsc = (w & 1) ? g_beta[rr * NVH + h] : g_ge[rr * NVH + h];
        }
    };

    auto stage = [&](int buf) {
        if (tid < 64) {
            const int st = tid >> 5, idx = tid & 31;
            *(float4*)&k_sm[buf][st][(idx >> 3) * 36 + ((idx * 4) & 31)] = lkq;
        } else {
            const int t2 = tid - 64, st = t2 >> 5, idx = t2 & 31;
            *(float4*)&q_sm[buf][st][(idx >> 3) * 36 + ((idx * 4) & 31)] = lkq;
        }
        if (tid < 16) {
            const int st = tid >> 3, idx = tid & 7;
            *(float4*)&v_sm[buf][st][idx * 4] = lv;
        } else if (tid < 20) {
            const int w = tid - 16;
            sc_sm[buf][w >> 1][w & 1] = lsc;
        }
    };

    auto dostep = [&](int buf, int st, int t) {
        const float g   = sc_sm[buf][st][0];
        const float bta = sc_sm[buf][st][1];
        const float vv  = v_sm[buf][st][vloc];
        const ulonglong2* kp2 = (const ulonglong2*)&k_sm[buf][st][ks * 36];
        const ulonglong2* qp2 = (const ulonglong2*)&q_sm[buf][st][ks * 36];

        unsigned long long kk[16];
#pragma unroll
        for (int j = 0; j < 8; j++) { ulonglong2 u = kp2[j]; kk[2*j] = u.x; kk[2*j+1] = u.y; }

        // dot with OLD (undecayed) state; apply g once after reduction
        unsigned long long ac[4] = {0ull, 0ull, 0ull, 0ull};
#pragma unroll
        for (int j = 0; j < 16; j++)
            ac[j & 3] = f2fma(kk[j], sp[j], ac[j & 3]);
        float kv, xl, xh;
        upk2(ac[0], xl, xh); kv = xl + xh;
        upk2(ac[1], xl, xh); kv += xl + xh;
        upk2(ac[2], xl, xh); kv += xl + xh;
        upk2(ac[3], xl, xh); kv += xl + xh;
        kv += __shfl_xor_sync(0xFFFFFFFFu, kv, 1);
        kv += __shfl_xor_sync(0xFFFFFFFFu, kv, 2);
        kv *= g;

        const float delta = bta * (vv - kv);
        const unsigned long long gg = pk2(g, g);
        const unsigned long long dd = pk2(delta, delta);

        unsigned long long qq[16];
#pragma unroll
        for (int j = 0; j < 8; j++) { ulonglong2 u = qp2[j]; qq[2*j] = u.x; qq[2*j+1] = u.y; }

        unsigned long long oc[4] = {0ull, 0ull, 0ull, 0ull};
#pragma unroll
        for (int j = 0; j < 16; j++) {
            sp[j] = f2mul(sp[j], gg);
            sp[j] = f2fma(kk[j], dd, sp[j]);
            oc[j & 3] = f2fma(qq[j], sp[j], oc[j & 3]);
        }
        float o;
        upk2(oc[0], xl, xh); o = xl + xh;
        upk2(oc[1], xl, xh); o += xl + xh;
        upk2(oc[2], xl, xh); o += xl + xh;
        upk2(oc[3], xl, xh); o += xl + xh;
        o += __shfl_xor_sync(0xFFFFFFFFu, o, 1);
        o += __shfl_xor_sync(0xFFFFFFFFu, o, 2);

        if (ks == 0)
            g_core[((size_t)b * SS + t) * VDIM + h * 128 + qt * 32 + vloc] = o;
    };

    prefetch(0);
    for (int t = 0; t < SS; t += 2) {
        const int buf = (t >> 1) & 1;
        stage(buf);
        if (t + 2 < SS) prefetch(t + 2);
        __syncthreads();
        dostep(buf, 0, t);
        dostep(buf, 1, t + 1);
    }
}

// =====================================================================
// RMSNorm(core) * (1+norm_w) * SiLU(z) -> g_gh (fp16)
// =====================================================================
__global__ __launch_bounds__(256) void rms_gate(const float* __restrict__ norm_w)
{
    const int row = blockIdx.x;
    const int tid = threadIdx.x;
    float vals[16];
    float ss = 0.f;
#pragma unroll
    for (int i = 0; i < 16; i++) {
        float v = g_core[(size_t)row * VDIM + i * 256 + tid];
        vals[i] = v;
        ss = fmaf(v, v, ss);
    }
    __shared__ float red[8];
#pragma unroll
    for (int off = 16; off; off >>= 1)
        ss += __shfl_xor_sync(0xFFFFFFFFu, ss, off);
    if ((tid & 31) == 0) red[tid >> 5] = ss;
    __syncthreads();
    float tot = 0.f;
#pragma unroll
    for (int w = 0; w < 8; w++) tot += red[w];
    const float rs = rsqrtf(tot / (float)VDIM + 1e-6f);
#pragma unroll
    for (int i = 0; i < 16; i++) {
        const int c = i * 256 + tid;
        float z  = __half2float(g_qkvz2[(size_t)row * PD2 + 8192 + c]);
        float sz = z / (1.f + expf(-z));
        g_gh[(size_t)row * VDIM + c] =
            __float2half_rn(vals[i] * rs * (1.f + norm_w[c]) * sz);
    }
}

// =====================================================================
extern "C" void kernel_launch(void* const* d_in, const int* in_sizes, int n_in,
                              void* d_out, int out_size)
{
    const float* x       = (const float*)d_in[0];
    const float* W_qkvz  = (const float*)d_in[1];
    const float* W_ba    = (const float*)d_in[2];
    const float* conv_w  = (const float*)d_in[3];
    const float* dt_bias = (const float*)d_in[4];
    const float* A_log   = (const float*)d_in[5];
    const float* norm_w  = (const float*)d_in[6];
    const float* W_out   = (const float*)d_in[7];
    float* out = (float*)d_out;

    __half *p_qkvz2, *p_xh, *p_wh1, *p_gh, *p_woh;
    cudaGetSymbolAddress((void**)&p_qkvz2, g_qkvz2);
    cudaGetSymbolAddress((void**)&p_xh,    g_xh);
    cudaGetSymbolAddress((void**)&p_wh1,   g_wh1);
    cudaGetSymbolAddress((void**)&p_gh,    g_gh);
    cudaGetSymbolAddress((void**)&p_woh,   g_woh);

    cudaFuncSetAttribute(gemm_f16<__half>, cudaFuncAttributeMaxDynamicSharedMemorySize, GSMEM);
    cudaFuncSetAttribute(gemm_f16<float>,  cudaFuncAttributeMaxDynamicSharedMemorySize, GSMEM);

    // 0) fp16 conversions
    cvt_x <<<2048, 256>>>(x);
    cvt_w1<<<4096, 256>>>(W_qkvz, W_ba);
    cvt_wo<<<2048, 256>>>(W_out);

    // 1) fused qkvz+ba GEMM -> fp16 buffer
    gemm_f16<__half><<<dim3(PD2 / 128, ROWS / 128), 256, GSMEM>>>(p_xh, p_wh1, p_qkvz2, ROWS, PD2, HID);

    // 2) conv + silu + l2norm split
    conv_norm<<<dim3(64, SS / SCHUNK, BB), 128>>>(conv_w);
    // 3) beta / exp(g)
    gate_prep<<<ROWS * NVH / 256, 256>>>(dt_bias, A_log);
    // 4) recurrent delta-rule scan (256 CTAs x 128 thr, 2 steps/barrier)
    scan_kernel<<<256, 128>>>();
    // 5) RMSNorm + gate -> fp16
    rms_gate<<<ROWS, 256>>>(norm_w);
    // 6) out = gated @ W_out^T  (fp32 out)
    gemm_f16<float><<<dim3(HID / 128, ROWS / 128), 256, GSMEM>>>(p_gh, p_woh, out, ROWS, HID, VDIM);
}

// round 10
// speedup vs baseline: 3.7019x; 1.0251x over previous
#include <cuda_runtime.h>
#include <cuda_fp16.h>
#include <cstdint>
#include <math.h>

// ---------------- problem dims ----------------
#define BB    2
#define SS    2048
#define HID   2048
#define VDIM  4096
#define KEYD  2048
#define NVH   32
#define ROWS  4096            // B*S
#define PD2   12416           // 12288 qkvz + 64 ba + 64 pad  (= 97*128)

// ---------------- static scratch ----------------
__device__ __half g_qkvz2[(size_t)ROWS * PD2];     // fp16 qkvz+ba fused output
__device__ float  g_qn  [(size_t)ROWS * KEYD];
__device__ float  g_kn  [(size_t)ROWS * KEYD];
__device__ float  g_v   [(size_t)ROWS * VDIM];
__device__ float  g_beta[ROWS * NVH];
__device__ float  g_ge  [ROWS * NVH];
__device__ float  g_core[(size_t)ROWS * VDIM];
__device__ __half g_xh  [(size_t)ROWS * HID];
__device__ __half g_wh1 [(size_t)PD2 * HID];
__device__ __half g_gh  [(size_t)ROWS * VDIM];
__device__ __half g_woh [(size_t)HID * VDIM];

// ---------------- helpers ----------------
__device__ __forceinline__ uint32_t smem_u32(const void* p) {
    uint32_t a;
    asm("{ .reg .u64 t; cvta.to.shared.u64 t, %1; cvt.u32.u64 %0, t; }" : "=r"(a) : "l"(p));
    return a;
}
#define SW128(o) ((o) ^ (((o) >> 3) & 0x70))

// f32x2 packed math
__device__ __forceinline__ unsigned long long pk2(float lo, float hi) {
    unsigned long long r; asm("mov.b64 %0, {%1, %2};" : "=l"(r) : "f"(lo), "f"(hi)); return r;
}
__device__ __forceinline__ void upk2(unsigned long long v, float& lo, float& hi) {
    asm("mov.b64 {%0, %1}, %2;" : "=f"(lo), "=f"(hi) : "l"(v));
}
__device__ __forceinline__ unsigned long long f2mul(unsigned long long a, unsigned long long b) {
    unsigned long long d; asm("mul.rn.f32x2 %0, %1, %2;" : "=l"(d) : "l"(a), "l"(b)); return d;
}
__device__ __forceinline__ unsigned long long f2fma(unsigned long long a, unsigned long long b, unsigned long long c) {
    unsigned long long d; asm("fma.rn.f32x2 %0, %1, %2, %3;" : "=l"(d) : "l"(a), "l"(b), "l"(c)); return d;
}

// =====================================================================
// fp16 tensor-core GEMM: C[M,N] = A[M,K] * B[N,K]^T
// 128x128 tile, K-stage 64, cp.async x3 stages, ldmatrix, mma.m16n8k16.
// =====================================================================
#define BKH   64
#define STG_B 32768
#define GSMEM (3 * STG_B)

template <typename OutT>
__global__ __launch_bounds__(256, 2) void gemm_f16(
    const __half* __restrict__ A, const __half* __restrict__ B,
    OutT* __restrict__ C, int M, int N, int K)
{
    extern __shared__ char sm[];
    const int tid  = threadIdx.x;
    const int warp = tid >> 5, lane = tid & 31;
    const int bm   = blockIdx.y * 128;
    const int bn   = blockIdx.x * 128;
    const int wm   = (warp & 1) * 64;
    const int wn   = (warp >> 1) * 32;

    auto loadStage = [&](int st, int kt) {
        char* as = sm + st * STG_B;
        char* bs = as + 16384;
#pragma unroll
        for (int j = 0; j < 4; j++) {
            const int idx = tid + j * 256;
            const int row = idx >> 3;
            const int c   = idx & 7;
            const uint32_t so = SW128((uint32_t)(row * 128 + c * 16));
            uint32_t da = smem_u32(as + so);
            const __half* sa = A + (size_t)(bm + row) * K + kt + c * 8;
            asm volatile("cp.async.cg.shared.global [%0], [%1], 16;" :: "r"(da), "l"(sa));
            uint32_t db = smem_u32(bs + so);
            const __half* sb = B + (size_t)(bn + row) * K + kt + c * 8;
            asm volatile("cp.async.cg.shared.global [%0], [%1], 16;" :: "r"(db), "l"(sb));
        }
        asm volatile("cp.async.commit_group;");
    };

    float acc[4][4][4];
#pragma unroll
    for (int i = 0; i < 4; i++)
#pragma unroll
        for (int j = 0; j < 4; j++)
#pragma unroll
            for (int r = 0; r < 4; r++) acc[i][j][r] = 0.f;

    const int S = K / BKH;
    loadStage(0, 0);
    loadStage(1, BKH);

    const int aRowOff = (lane & 7) + ((lane >> 3) & 1) * 8;
    const int aKOff   = (lane >> 4) * 16;
    const int bRow2   = (lane & 7) + ((lane >> 4) * 8);
    const int bK2     = ((lane >> 3) & 1) * 16;

    for (int s = 0; s < S; s++) {
        if (s + 1 < S) asm volatile("cp.async.wait_group 1;" ::: "memory");
        else           asm volatile("cp.async.wait_group 0;" ::: "memory");
        __syncthreads();
        if (s + 2 < S) loadStage((s + 2) % 3, (s + 2) * BKH);

        const uint32_t aBase = smem_u32(sm + (s % 3) * STG_B);
        const uint32_t bBase = aBase + 16384;

#pragma unroll
        for (int kb = 0; kb < 4; kb++) {
            uint32_t af[4][4], bf[2][4];
#pragma unroll
            for (int i = 0; i < 4; i++) {
                const uint32_t ad = aBase +
                    SW128((uint32_t)((wm + i * 16 + aRowOff) * 128 + kb * 32 + aKOff));
                asm volatile("ldmatrix.sync.aligned.m8n8.x4.shared.b16 {%0,%1,%2,%3}, [%4];"
                    : "=r"(af[i][0]), "=r"(af[i][1]), "=r"(af[i][2]), "=r"(af[i][3]) : "r"(ad));
            }
#pragma unroll
            for (int p = 0; p < 2; p++) {
                const uint32_t bd = bBase +
                    SW128((uint32_t)((wn + p * 16 + bRow2) * 128 + kb * 32 + bK2));
                asm volatile("ldmatrix.sync.aligned.m8n8.x4.shared.b16 {%0,%1,%2,%3}, [%4];"
                    : "=r"(bf[p][0]), "=r"(bf[p][1]), "=r"(bf[p][2]), "=r"(bf[p][3]) : "r"(bd));
            }
#pragma unroll
            for (int i = 0; i < 4; i++)
#pragma unroll
                for (int j = 0; j < 4; j++)
                    asm volatile(
                        "mma.sync.aligned.m16n8k16.row.col.f32.f16.f16.f32 "
                        "{%0,%1,%2,%3}, {%4,%5,%6,%7}, {%8,%9}, {%0,%1,%2,%3};"
                        : "+f"(acc[i][j][0]), "+f"(acc[i][j][1]),
                          "+f"(acc[i][j][2]), "+f"(acc[i][j][3])
                        : "r"(af[i][0]), "r"(af[i][1]), "r"(af[i][2]), "r"(af[i][3]),
                          "r"(bf[j >> 1][(j & 1) * 2]), "r"(bf[j >> 1][(j & 1) * 2 + 1]));
        }
    }

#pragma unroll
    for (int i = 0; i < 4; i++)
#pragma unroll
        for (int j = 0; j < 4; j++) {
            const int r = bm + wm + i * 16 + (lane >> 2);
            const int c = bn + wn + j * 8 + (lane & 3) * 2;
            if (sizeof(OutT) == 2) {
                __half2* d0 = (__half2*)((__half*)C + (size_t)r * N + c);
                __half2* d1 = (__half2*)((__half*)C + (size_t)(r + 8) * N + c);
                *d0 = __floats2half2_rn(acc[i][j][0], acc[i][j][1]);
                *d1 = __floats2half2_rn(acc[i][j][2], acc[i][j][3]);
            } else {
                float2 v0; v0.x = acc[i][j][0]; v0.y = acc[i][j][1];
                float2 v1; v1.x = acc[i][j][2]; v1.y = acc[i][j][3];
                *(float2*)((float*)C + (size_t)r * N + c)       = v0;
                *(float2*)((float*)C + (size_t)(r + 8) * N + c) = v1;
            }
        }
}

// =====================================================================
// conversions to fp16
// =====================================================================
__global__ __launch_bounds__(256) void cvt_x(const float* __restrict__ x)
{
    const size_t n = (size_t)ROWS * HID;
    for (size_t i = (size_t)blockIdx.x * 256 + threadIdx.x; i < n; i += (size_t)gridDim.x * 256)
        g_xh[i] = __float2half_rn(x[i]);
}
__global__ __launch_bounds__(256) void cvt_w1(
    const float* __restrict__ Wq, const float* __restrict__ Wb)
{
    const size_t n = (size_t)PD2 * HID;
    for (size_t i = (size_t)blockIdx.x * 256 + threadIdx.x; i < n; i += (size_t)gridDim.x * 256) {
        const int row = (int)(i >> 11);
        const int col = (int)(i & 2047);
        float v;
        if (row < 12288)      v = Wq[i];
        else if (row < 12352) v = Wb[(size_t)(row - 12288) * HID + col];
        else                  v = 0.f;
        g_wh1[i] = __float2half_rn(v);
    }
}
__global__ __launch_bounds__(256) void cvt_wo(const float* __restrict__ Wo)
{
    const size_t n = (size_t)HID * VDIM;
    for (size_t i = (size_t)blockIdx.x * 256 + threadIdx.x; i < n; i += (size_t)gridDim.x * 256)
        g_woh[i] = __float2half_rn(Wo[i]);
}

// =====================================================================
// Sliding-window causal conv (K=4) + SiLU + l2norm split (fp16 input)
// =====================================================================
#define SCHUNK 128

__global__ __launch_bounds__(128) void conv_norm(const float* __restrict__ conv_w)
{
    const int tid = threadIdx.x;
    const int c   = blockIdx.x * 128 + tid;
    const int s0  = blockIdx.y * SCHUNK;
    const int b   = blockIdx.z;
    const bool isqk = (blockIdx.x < 32);

    __shared__ float red[2][4];

    const float w0 = conv_w[c * 4 + 0], w1 = conv_w[c * 4 + 1];
    const float w2 = conv_w[c * 4 + 2], w3 = conv_w[c * 4 + 3];

    const __half* src = g_qkvz2 + (size_t)(b * SS) * PD2 + c;

    float xm3 = (s0 >= 3) ? __half2float(src[(size_t)(s0 - 3) * PD2]) : 0.f;
    float xm2 = (s0 >= 2) ? __half2float(src[(size_t)(s0 - 2) * PD2]) : 0.f;
    float xm1 = (s0 >= 1) ? __half2float(src[(size_t)(s0 - 1) * PD2]) : 0.f;
    float cur = __half2float(src[(size_t)s0 * PD2]);

    for (int i = 0; i < SCHUNK; i++) {
        const int s = s0 + i;
        float nxt = 0.f;
        if (i + 1 < SCHUNK) nxt = __half2float(src[(size_t)(s + 1) * PD2]);

        float acc = w3 * cur;
        acc = fmaf(w2, xm1, acc);
        acc = fmaf(w1, xm2, acc);
        acc = fmaf(w0, xm3, acc);
        xm3 = xm2; xm2 = xm1; xm1 = cur; cur = nxt;

        const float val = acc / (1.f + expf(-acc));
        const size_t row = (size_t)b * SS + s;

        if (isqk) {
            float ss = val * val;
#pragma unroll
            for (int off = 16; off; off >>= 1)
                ss += __shfl_xor_sync(0xFFFFFFFFu, ss, off);
            if ((tid & 31) == 0) red[i & 1][tid >> 5] = ss;
            __syncthreads();
            const float tot = red[i & 1][0] + red[i & 1][1] + red[i & 1][2] + red[i & 1][3];
            const float o = val * rsqrtf(tot + 1e-6f);
            if (c < KEYD) g_qn[row * KEYD + c]          = o;
            else          g_kn[row * KEYD + (c - KEYD)] = o;
        } else {
            g_v[row * VDIM + (c - 2 * KEYD)] = val;
        }
    }
}

// =====================================================================
// beta = sigmoid(b); ge = exp(-exp(A_log)*softplus(a+dt_bias))
// =====================================================================
__global__ __launch_bounds__(256) void gate_prep(
    const float* __restrict__ dt_bias, const float* __restrict__ A_log)
{
    const int idx = blockIdx.x * 256 + threadIdx.x;
    const int row = idx >> 5, h = idx & 31;
    float bv = __half2float(g_qkvz2[(size_t)row * PD2 + 12288 + h]);
    float av = __half2float(g_qkvz2[(size_t)row * PD2 + 12320 + h]);
    float beta = 1.f / (1.f + expf(-bv));
    float xx = av + dt_bias[h];
    float sp = xx > 20.f ? xx : log1pf(expf(xx));
    float g  = -expf(A_log[h]) * sp;
    g_beta[row * NVH + h] = beta;
    g_ge[row * NVH + h]   = expf(g);
}

// =====================================================================
// Gated delta-rule scan, f32x2. 512 CTAs = (b, h, eighth). 64 threads.
// Two time steps per barrier; barrier couples only 2 warps.
// tid = vloc*4 + ks : thread owns k-slice [ks*32,+32) of column vloc (0..15).
// =====================================================================
__global__ __launch_bounds__(64, 4) void scan_kernel()
{
    __shared__ __align__(16) float k_sm[2][2][144];
    __shared__ __align__(16) float q_sm[2][2][144];
    __shared__ float v_sm[2][2][16];
    __shared__ float sc_sm[2][2][2];

    const int bx  = blockIdx.x;          // 0..511
    const int b   = bx >> 8;
    const int h   = (bx >> 3) & 31;
    const int qt  = bx & 7;              // eighth of DV: 16 cols
    const int kh  = h >> 1;
    const int tid = threadIdx.x;
    const int vloc = tid >> 2;           // 0..15
    const int ks   = tid & 3;

    unsigned long long sp[16];
#pragma unroll
    for (int i = 0; i < 16; i++) sp[i] = 0ull;

    float4 lk = {0,0,0,0}, lq = {0,0,0,0}, lv = {0,0,0,0};
    float  lsc = 0.f;
    const int st  = tid >> 5;            // which of the 2 staged steps
    const int idx = tid & 31;            // float4 index within a row

    auto prefetch = [&](int t) {
        const size_t rb = (size_t)b * SS;
        lk = *(const float4*)(g_kn + (rb + t + st) * KEYD + kh * 128 + idx * 4);
        lq = *(const float4*)(g_qn + (rb + t + st) * KEYD + kh * 128 + idx * 4);
        if (tid < 8)
            lv = *(const float4*)(g_v + (rb + t + (tid >> 2)) * VDIM + h * 128 + qt * 16 + (tid & 3) * 4);
        if (tid < 4) {
            const size_t rr = rb + t + (tid >> 1);
            lsc = (tid & 1) ? g_beta[rr * NVH + h] : g_ge[rr * NVH + h];
        }
    };

    auto stage = [&](int buf) {
        *(float4*)&k_sm[buf][st][(idx >> 3) * 36 + ((idx * 4) & 31)] = lk;
        *(float4*)&q_sm[buf][st][(idx >> 3) * 36 + ((idx * 4) & 31)] = lq;
        if (tid < 8)
            *(float4*)&v_sm[buf][tid >> 2][(tid & 3) * 4] = lv;
        if (tid < 4)
            sc_sm[buf][tid >> 1][tid & 1] = lsc;
    };

    auto dostep = [&](int buf, int s2, int t) {
        const float g   = sc_sm[buf][s2][0];
        const float bta = sc_sm[buf][s2][1];
        const float vv  = v_sm[buf][s2][vloc];
        const ulonglong2* kp2 = (const ulonglong2*)&k_sm[buf][s2][ks * 36];
        const ulonglong2* qp2 = (const ulonglong2*)&q_sm[buf][s2][ks * 36];

        unsigned long long kk[16];
#pragma unroll
        for (int j = 0; j < 8; j++) { ulonglong2 u = kp2[j]; kk[2*j] = u.x; kk[2*j+1] = u.y; }

        unsigned long long ac[4] = {0ull, 0ull, 0ull, 0ull};
#pragma unroll
        for (int j = 0; j < 16; j++)
            ac[j & 3] = f2fma(kk[j], sp[j], ac[j & 3]);
        float kv, xl, xh;
        upk2(ac[0], xl, xh); kv = xl + xh;
        upk2(ac[1], xl, xh); kv += xl + xh;
        upk2(ac[2], xl, xh); kv += xl + xh;
        upk2(ac[3], xl, xh); kv += xl + xh;
        kv += __shfl_xor_sync(0xFFFFFFFFu, kv, 1);
        kv += __shfl_xor_sync(0xFFFFFFFFu, kv, 2);
        kv *= g;

        const float delta = bta * (vv - kv);
        const unsigned long long gg = pk2(g, g);
        const unsigned long long dd = pk2(delta, delta);

        unsigned long long qq[16];
#pragma unroll
        for (int j = 0; j < 8; j++) { ulonglong2 u = qp2[j]; qq[2*j] = u.x; qq[2*j+1] = u.y; }

        unsigned long long oc[4] = {0ull, 0ull, 0ull, 0ull};
#pragma unroll
        for (int j = 0; j < 16; j++) {
            sp[j] = f2mul(sp[j], gg);
            sp[j] = f2fma(kk[j], dd, sp[j]);
            oc[j & 3] = f2fma(qq[j], sp[j], oc[j & 3]);
        }
        float o;
        upk2(oc[0], xl, xh); o = xl + xh;
        upk2(oc[1], xl, xh); o += xl + xh;
        upk2(oc[2], xl, xh); o += xl + xh;
        upk2(oc[3], xl, xh); o += xl + xh;
        o += __shfl_xor_sync(0xFFFFFFFFu, o, 1);
        o += __shfl_xor_sync(0xFFFFFFFFu, o, 2);

        if (ks == 0)
            g_core[((size_t)b * SS + t) * VDIM + h * 128 + qt * 16 + vloc] = o;
    };

    prefetch(0);
    for (int t = 0; t < SS; t += 2) {
        const int buf = (t >> 1) & 1;
        stage(buf);
        if (t + 2 < SS) prefetch(t + 2);
        __syncthreads();
        dostep(buf, 0, t);
        dostep(buf, 1, t + 1);
    }
}

// =====================================================================
// RMSNorm(core) * (1+norm_w) * SiLU(z) -> g_gh (fp16)
// =====================================================================
__global__ __launch_bounds__(256) void rms_gate(const float* __restrict__ norm_w)
{
    const int row = blockIdx.x;
    const int tid = threadIdx.x;
    float vals[16];
    float ss = 0.f;
#pragma unroll
    for (int i = 0; i < 16; i++) {
        float v = g_core[(size_t)row * VDIM + i * 256 + tid];
        vals[i] = v;
        ss = fmaf(v, v, ss);
    }
    __shared__ float red[8];
#pragma unroll
    for (int off = 16; off; off >>= 1)
        ss += __shfl_xor_sync(0xFFFFFFFFu, ss, off);
    if ((tid & 31) == 0) red[tid >> 5] = ss;
    __syncthreads();
    float tot = 0.f;
#pragma unroll
    for (int w = 0; w < 8; w++) tot += red[w];
    const float rs = rsqrtf(tot / (float)VDIM + 1e-6f);
#pragma unroll
    for (int i = 0; i < 16; i++) {
        const int c = i * 256 + tid;
        float z  = __half2float(g_qkvz2[(size_t)row * PD2 + 8192 + c]);
        float sz = z / (1.f + expf(-z));
        g_gh[(size_t)row * VDIM + c] =
            __float2half_rn(vals[i] * rs * (1.f + norm_w[c]) * sz);
    }
}

// =====================================================================
extern "C" void kernel_launch(void* const* d_in, const int* in_sizes, int n_in,
                              void* d_out, int out_size)
{
    const float* x       = (const float*)d_in[0];
    const float* W_qkvz  = (const float*)d_in[1];
    const float* W_ba    = (const float*)d_in[2];
    const float* conv_w  = (const float*)d_in[3];
    const float* dt_bias = (const float*)d_in[4];
    const float* A_log   = (const float*)d_in[5];
    const float* norm_w  = (const float*)d_in[6];
    const float* W_out   = (const float*)d_in[7];
    float* out = (float*)d_out;

    __half *p_qkvz2, *p_xh, *p_wh1, *p_gh, *p_woh;
    cudaGetSymbolAddress((void**)&p_qkvz2, g_qkvz2);
    cudaGetSymbolAddress((void**)&p_xh,    g_xh);
    cudaGetSymbolAddress((void**)&p_wh1,   g_wh1);
    cudaGetSymbolAddress((void**)&p_gh,    g_gh);
    cudaGetSymbolAddress((void**)&p_woh,   g_woh);

    cudaFuncSetAttribute(gemm_f16<__half>, cudaFuncAttributeMaxDynamicSharedMemorySize, GSMEM);
    cudaFuncSetAttribute(gemm_f16<float>,  cudaFuncAttributeMaxDynamicSharedMemorySize, GSMEM);

    // 0) fp16 conversions
    cvt_x <<<2048, 256>>>(x);
    cvt_w1<<<4096, 256>>>(W_qkvz, W_ba);
    cvt_wo<<<2048, 256>>>(W_out);

    // 1) fused qkvz+ba GEMM -> fp16 buffer
    gemm_f16<__half><<<dim3(PD2 / 128, ROWS / 128), 256, GSMEM>>>(p_xh, p_wh1, p_qkvz2, ROWS, PD2, HID);

    // 2) conv + silu + l2norm split
    conv_norm<<<dim3(64, SS / SCHUNK, BB), 128>>>(conv_w);
    // 3) beta / exp(g)
    gate_prep<<<ROWS * NVH / 256, 256>>>(dt_bias, A_log);
    // 4) recurrent delta-rule scan (512 CTAs x 64 thr, 2 steps/barrier)
    scan_kernel<<<512, 64>>>();
    // 5) RMSNorm + gate -> fp16
    rms_gate<<<ROWS, 256>>>(norm_w);
    // 6) out = gated @ W_out^T  (fp32 out)
    gemm_f16<float><<<dim3(HID / 128, ROWS / 128), 256, GSMEM>>>(p_gh, p_woh, out, ROWS, HID, VDIM);
}